// round 2
// baseline (speedup 1.0000x reference)
#include <cuda_runtime.h>

#define NA 8192
#define NN 65536
#define NE 262144
#define D  128
#define NB 2
#define TILE 32
#define EPS 1e-5f

// ---------------- scratch (device globals; no allocation allowed) ------------
__device__ float g_q[NA * D];    // relu(GN(actors @ Wq^T)) table
__device__ float g_a[NA * D];    // actors @ Wagt^T, accumulates edge messages
__device__ float g_x[NA * D];    // relu(GN(a))
__device__ float g_act[NA * D];  // inter-block actors

// =============================================================================
// Tiled GEMM: out[TILE][128] = in[TILE][K] @ W[128][K]^T
// 256 threads; thread (jb = tid&31, eb = tid>>5) computes 4x4 micro-tile.
// W staged per 32-k chunk into sW[kk][j] (transposed) in shared.
// sW and sOut may alias (write happens after a final sync).
// =============================================================================
template <int K, int SSTR>
__device__ __forceinline__ void tile_gemm(const float* __restrict__ W,
                                          const float* sIn, float* sOut,
                                          float* sW) {
    const int tid = threadIdx.x;
    const int jb = tid & 31;   // columns jb*4 .. jb*4+3
    const int eb = tid >> 5;   // rows    eb*4 .. eb*4+3
    float acc[4][4];
#pragma unroll
    for (int i = 0; i < 4; i++)
#pragma unroll
        for (int j = 0; j < 4; j++) acc[i][j] = 0.0f;

    for (int k0 = 0; k0 < K; k0 += 32) {
        __syncthreads();  // protect sW (and aliased sOut) from previous readers
        {
            // stage: sW[kk*128 + j] = W[j*K + k0 + kk]
            const int j = tid >> 1;
            const int kk0 = (tid & 1) << 4;
            const float4* Wr = reinterpret_cast<const float4*>(W + j * K + k0 + kk0);
#pragma unroll
            for (int i = 0; i < 4; i++) {
                float4 v = Wr[i];
                int kk = kk0 + i * 4;
                sW[kk * 128 + j]       = v.x;
                sW[(kk + 1) * 128 + j] = v.y;
                sW[(kk + 2) * 128 + j] = v.z;
                sW[(kk + 3) * 128 + j] = v.w;
            }
        }
        __syncthreads();
#pragma unroll
        for (int kk = 0; kk < 32; kk += 4) {
            float4 a4[4];
#pragma unroll
            for (int i = 0; i < 4; i++)
                a4[i] = *reinterpret_cast<const float4*>(sIn + (eb * 4 + i) * SSTR + k0 + kk);
#pragma unroll
            for (int t = 0; t < 4; t++) {
                float4 bv = *reinterpret_cast<const float4*>(sW + (kk + t) * 128 + jb * 4);
#pragma unroll
                for (int i = 0; i < 4; i++) {
                    float av = (t == 0) ? a4[i].x : (t == 1) ? a4[i].y
                             : (t == 2) ? a4[i].z : a4[i].w;
                    acc[i][0] = fmaf(av, bv.x, acc[i][0]);
                    acc[i][1] = fmaf(av, bv.y, acc[i][1]);
                    acc[i][2] = fmaf(av, bv.z, acc[i][2]);
                    acc[i][3] = fmaf(av, bv.w, acc[i][3]);
                }
            }
        }
    }
    __syncthreads();  // all sW reads done before (possibly aliased) sOut write
#pragma unroll
    for (int i = 0; i < 4; i++) {
        float4 v = make_float4(acc[i][0], acc[i][1], acc[i][2], acc[i][3]);
        *reinterpret_cast<float4*>(sOut + (eb * 4 + i) * 128 + jb * 4) = v;
    }
}

// GroupNorm (1 group over 128 channels) per row of sOut -> sDst[row*stride + c]
__device__ __forceinline__ void tile_gn_to_smem(const float* sOut,
                                                const float* __restrict__ g,
                                                const float* __restrict__ bb,
                                                float* sDst, int dstStride,
                                                bool doRelu) {
    const int tid = threadIdx.x;
    const int warp = tid >> 5, lane = tid & 31;
    const float g0 = g[lane], g1 = g[lane + 32], g2 = g[lane + 64], g3 = g[lane + 96];
    const float b0 = bb[lane], b1 = bb[lane + 32], b2 = bb[lane + 64], b3 = bb[lane + 96];
    for (int e = warp; e < TILE; e += 8) {
        float v0 = sOut[e * 128 + lane];
        float v1 = sOut[e * 128 + lane + 32];
        float v2 = sOut[e * 128 + lane + 64];
        float v3 = sOut[e * 128 + lane + 96];
        float s = v0 + v1 + v2 + v3;
        float q = fmaf(v0, v0, fmaf(v1, v1, fmaf(v2, v2, v3 * v3)));
#pragma unroll
        for (int o = 16; o > 0; o >>= 1) {
            s += __shfl_xor_sync(0xffffffffu, s, o);
            q += __shfl_xor_sync(0xffffffffu, q, o);
        }
        float mu = s * (1.0f / 128.0f);
        float rs = rsqrtf(q * (1.0f / 128.0f) - mu * mu + EPS);
        float y0 = (v0 - mu) * rs * g0 + b0;
        float y1 = (v1 - mu) * rs * g1 + b1;
        float y2 = (v2 - mu) * rs * g2 + b2;
        float y3 = (v3 - mu) * rs * g3 + b3;
        if (doRelu) {
            y0 = fmaxf(y0, 0.0f); y1 = fmaxf(y1, 0.0f);
            y2 = fmaxf(y2, 0.0f); y3 = fmaxf(y3, 0.0f);
        }
        sDst[e * dstStride + lane]      = y0;
        sDst[e * dstStride + lane + 32] = y1;
        sDst[e * dstStride + lane + 64] = y2;
        sDst[e * dstStride + lane + 96] = y3;
    }
}

// =============================================================================
// Fused edge kernel: per 32-edge tile
//   h = relu(d2 @ W0^T + b0)
//   d = relu(GN(h @ W1^T))
//   u = relu(GN([d,q,c] @ Wc0^T))
//   m = u @ Wc1^T
//   atomicAdd(g_a[hi], m)
// shared: sIn[TILE][384] (concat buffer), sWO[32][128] (W-chunk / output union)
// =============================================================================
__global__ void __launch_bounds__(256) edge_kernel(
    const float* __restrict__ actor_ctrs, const float* __restrict__ node_ctrs,
    const int* __restrict__ hi, const int* __restrict__ wi,
    const float* __restrict__ nodes,
    const float* __restrict__ W0, const float* __restrict__ b0,
    const float* __restrict__ W1, const float* __restrict__ g1, const float* __restrict__ b1,
    const float* __restrict__ Wc0, const float* __restrict__ gc0, const float* __restrict__ bc0,
    const float* __restrict__ Wc1) {
    extern __shared__ float smem[];
    float* sIn = smem;               // TILE*384
    float* sWO = smem + TILE * 384;  // 32*128 (sW and sOut union)
    __shared__ int sHi[TILE], sWi[TILE];
    __shared__ float sW0[2 * D], sB0[D];

    const int tid = threadIdx.x;
    const int e0 = blockIdx.x * TILE;

    if (tid < TILE) { sHi[tid] = hi[e0 + tid]; sWi[tid] = wi[e0 + tid]; }
    sW0[tid] = W0[tid];  // 256 threads == 2*D
    if (tid < D) sB0[tid] = b0[tid];
    __syncthreads();

    // stage: h -> sIn[:,0:128], q -> sIn[:,128:256], c -> sIn[:,256:384]
    {
        const int e = tid >> 3;     // 0..31
        const int seg = tid & 7;    // 0..7, 16 floats each
        const int h = sHi[e], w = sWi[e];
        const float dx = actor_ctrs[h * 2]     - node_ctrs[w * 2];
        const float dy = actor_ctrs[h * 2 + 1] - node_ctrs[w * 2 + 1];
        const float4* qr = reinterpret_cast<const float4*>(g_q + h * D) + seg * 4;
        const float4* cr = reinterpret_cast<const float4*>(nodes + w * D) + seg * 4;
        float4* dq = reinterpret_cast<float4*>(sIn + e * 384 + 128) + seg * 4;
        float4* dc = reinterpret_cast<float4*>(sIn + e * 384 + 256) + seg * 4;
#pragma unroll
        for (int i = 0; i < 4; i++) { dq[i] = qr[i]; dc[i] = cr[i]; }
#pragma unroll
        for (int i = 0; i < 16; i++) {
            int k = seg * 16 + i;
            float hv = fmaf(dx, sW0[2 * k], fmaf(dy, sW0[2 * k + 1], sB0[k]));
            sIn[e * 384 + k] = fmaxf(hv, 0.0f);
        }
    }
    __syncthreads();

    tile_gemm<128, 384>(W1, sIn, sWO, sWO);          // t = h @ W1^T
    __syncthreads();
    tile_gn_to_smem(sWO, g1, b1, sIn, 384, true);    // d -> sIn[:,0:128]
    __syncthreads();
    tile_gemm<384, 384>(Wc0, sIn, sWO, sWO);         // [d,q,c] @ Wc0^T
    __syncthreads();
    tile_gn_to_smem(sWO, gc0, bc0, sIn, 384, true);  // u -> sIn[:,0:128]
    __syncthreads();
    tile_gemm<128, 384>(Wc1, sIn, sWO, sWO);         // m = u @ Wc1^T
    __syncthreads();

    // scatter-add into g_a
    {
        const int e = tid >> 3, seg = tid & 7;
        const int h = sHi[e];
        float* dst = g_a + h * D + seg * 16;
        const float* src = sWO + e * 128 + seg * 16;
#pragma unroll
        for (int i = 0; i < 16; i++) atomicAdd(dst + i, src[i]);
    }
}

// =============================================================================
// Actor-side row GEMM: out = f(in @ W^T), optional GN / relu / +res.
// For C2 (lin): out = relu(GN(x@W^T) + res). For q: relu(GN(..)). For agt: raw.
// =============================================================================
template <bool GN, bool RELU, bool RES>
__global__ void __launch_bounds__(256) rowgemm_kernel(
    const float* __restrict__ in, const float* __restrict__ W,
    const float* __restrict__ g, const float* __restrict__ bb,
    const float* __restrict__ res, float* __restrict__ out) {
    __shared__ float sIn[TILE * 128];
    __shared__ float sWO[32 * 128];
    const int tid = threadIdx.x;
    const int r0 = blockIdx.x * TILE;
    {
        const int r = tid >> 3, seg = tid & 7;
        const float4* src = reinterpret_cast<const float4*>(in + (r0 + r) * D) + seg * 4;
        float4* dst = reinterpret_cast<float4*>(sIn + r * 128) + seg * 4;
#pragma unroll
        for (int i = 0; i < 4; i++) dst[i] = src[i];
    }
    __syncthreads();
    tile_gemm<128, 128>(W, sIn, sWO, sWO);
    __syncthreads();
    if (GN) {
        const int warp = tid >> 5, lane = tid & 31;
        const float gg0 = g[lane], gg1 = g[lane + 32], gg2 = g[lane + 64], gg3 = g[lane + 96];
        const float bb0 = bb[lane], bb1 = bb[lane + 32], bb2 = bb[lane + 64], bb3 = bb[lane + 96];
        for (int e = warp; e < TILE; e += 8) {
            float v0 = sWO[e * 128 + lane];
            float v1 = sWO[e * 128 + lane + 32];
            float v2 = sWO[e * 128 + lane + 64];
            float v3 = sWO[e * 128 + lane + 96];
            float s = v0 + v1 + v2 + v3;
            float q = fmaf(v0, v0, fmaf(v1, v1, fmaf(v2, v2, v3 * v3)));
#pragma unroll
            for (int o = 16; o > 0; o >>= 1) {
                s += __shfl_xor_sync(0xffffffffu, s, o);
                q += __shfl_xor_sync(0xffffffffu, q, o);
            }
            float mu = s * (1.0f / 128.0f);
            float rs = rsqrtf(q * (1.0f / 128.0f) - mu * mu + EPS);
            float y0 = (v0 - mu) * rs * gg0 + bb0;
            float y1 = (v1 - mu) * rs * gg1 + bb1;
            float y2 = (v2 - mu) * rs * gg2 + bb2;
            float y3 = (v3 - mu) * rs * gg3 + bb3;
            const long rb = (long)(r0 + e) * D;
            if (RES) {
                y0 += res[rb + lane];      y1 += res[rb + lane + 32];
                y2 += res[rb + lane + 64]; y3 += res[rb + lane + 96];
            }
            if (RELU) {
                y0 = fmaxf(y0, 0.0f); y1 = fmaxf(y1, 0.0f);
                y2 = fmaxf(y2, 0.0f); y3 = fmaxf(y3, 0.0f);
            }
            out[rb + lane]      = y0;
            out[rb + lane + 32] = y1;
            out[rb + lane + 64] = y2;
            out[rb + lane + 96] = y3;
        }
    } else {
        const int r = tid >> 3, seg = tid & 7;
        float4* dst = reinterpret_cast<float4*>(out + (r0 + r) * D) + seg * 4;
        const float4* src = reinterpret_cast<const float4*>(sWO + r * 128) + seg * 4;
#pragma unroll
        for (int i = 0; i < 4; i++) dst[i] = src[i];
    }
}

// C1: x = relu(GN(a)) ; one warp per row
__global__ void __launch_bounds__(256) gnrows_kernel(
    const float* __restrict__ in, const float* __restrict__ g,
    const float* __restrict__ bb, float* __restrict__ out) {
    const int lane = threadIdx.x & 31;
    const int row = blockIdx.x * 8 + (threadIdx.x >> 5);
    const float* x = in + (long)row * D;
    float v0 = x[lane], v1 = x[lane + 32], v2 = x[lane + 64], v3 = x[lane + 96];
    float s = v0 + v1 + v2 + v3;
    float q = fmaf(v0, v0, fmaf(v1, v1, fmaf(v2, v2, v3 * v3)));
#pragma unroll
    for (int o = 16; o > 0; o >>= 1) {
        s += __shfl_xor_sync(0xffffffffu, s, o);
        q += __shfl_xor_sync(0xffffffffu, q, o);
    }
    float mu = s * (1.0f / 128.0f);
    float rs = rsqrtf(q * (1.0f / 128.0f) - mu * mu + EPS);
    float* o_ = out + (long)row * D;
    o_[lane]      = fmaxf((v0 - mu) * rs * g[lane] + bb[lane], 0.0f);
    o_[lane + 32] = fmaxf((v1 - mu) * rs * g[lane + 32] + bb[lane + 32], 0.0f);
    o_[lane + 64] = fmaxf((v2 - mu) * rs * g[lane + 64] + bb[lane + 64], 0.0f);
    o_[lane + 96] = fmaxf((v3 - mu) * rs * g[lane + 96] + bb[lane + 96], 0.0f);
}

#define EDGE_SMEM ((TILE * 384 + 32 * 128) * 4)

extern "C" void kernel_launch(void* const* d_in, const int* in_sizes, int n_in,
                              void* d_out, int out_size) {
    (void)in_sizes; (void)n_in; (void)out_size;
    const float* actors     = (const float*)d_in[0];
    const float* nodes      = (const float*)d_in[1];
    const float* actor_ctrs = (const float*)d_in[2];
    const float* node_ctrs  = (const float*)d_in[3];
    const int*   hi         = (const int*)d_in[4];
    const int*   wi         = (const int*)d_in[5];
    const float* dist0_W = (const float*)d_in[6];
    const float* dist0_b = (const float*)d_in[7];
    const float* dist1_W = (const float*)d_in[8];
    const float* dist1_g = (const float*)d_in[9];
    const float* dist1_b = (const float*)d_in[10];
    const float* query_W = (const float*)d_in[11];
    const float* query_g = (const float*)d_in[12];
    const float* query_b = (const float*)d_in[13];
    const float* ctx0_W  = (const float*)d_in[14];
    const float* ctx0_g  = (const float*)d_in[15];
    const float* ctx0_b  = (const float*)d_in[16];
    const float* ctx1_W  = (const float*)d_in[17];
    const float* agt_W   = (const float*)d_in[18];
    const float* norm_g  = (const float*)d_in[19];
    const float* norm_b  = (const float*)d_in[20];
    const float* lin_W   = (const float*)d_in[21];
    const float* lin_g   = (const float*)d_in[22];
    const float* lin_b   = (const float*)d_in[23];
    float* outp = (float*)d_out;

    void *pq_, *pa_, *px_, *pact_;
    cudaGetSymbolAddress(&pq_, g_q);
    cudaGetSymbolAddress(&pa_, g_a);
    cudaGetSymbolAddress(&px_, g_x);
    cudaGetSymbolAddress(&pact_, g_act);
    float* p_q   = (float*)pq_;
    float* p_a   = (float*)pa_;
    float* p_x   = (float*)px_;
    float* p_act = (float*)pact_;

    cudaFuncSetAttribute(edge_kernel, cudaFuncAttributeMaxDynamicSharedMemorySize, EDGE_SMEM);

    for (int i = 0; i < NB; i++) {
        const float* cur = (i == 0) ? actors : p_act;
        float* nxt = (i == NB - 1) ? outp : p_act;

        // q table: relu(GN(actors @ Wq^T))
        rowgemm_kernel<true, true, false><<<NA / TILE, 256>>>(
            cur, query_W + i * D * D, query_g + i * D, query_b + i * D, nullptr, p_q);
        // a = actors @ Wagt^T
        rowgemm_kernel<false, false, false><<<NA / TILE, 256>>>(
            cur, agt_W + i * D * D, nullptr, nullptr, nullptr, p_a);
        // fused edge chain + scatter-add into a
        edge_kernel<<<NE / TILE, 256, EDGE_SMEM>>>(
            actor_ctrs, node_ctrs, hi, wi, nodes,
            dist0_W + i * D * 2, dist0_b + i * D,
            dist1_W + i * D * D, dist1_g + i * D, dist1_b + i * D,
            ctx0_W + i * D * 3 * D, ctx0_g + i * D, ctx0_b + i * D,
            ctx1_W + i * D * D);
        // x = relu(GN(a))
        gnrows_kernel<<<NA / 8, 256>>>(p_a, norm_g + i * D, norm_b + i * D, p_x);
        // out = relu(GN(x @ Wlin^T) + res)
        rowgemm_kernel<true, true, true><<<NA / TILE, 256>>>(
            p_x, lin_W + i * D * D, lin_g + i * D, lin_b + i * D, cur, nxt);
    }
}

// round 4
// speedup vs baseline: 3.0315x; 3.0315x over previous
#include <cuda_runtime.h>
#include <cstdint>

#define NA 8192
#define NN 65536
#define NE 262144
#define D  128
#define NB 2
#define TILE 32
#define MT  128          // edges per edge-CTA
#define SA  68           // smem pair stride (64 pairs + 4 pad -> conflict-free)
#define EPS 1e-5f

// ---------------- scratch (device globals; no allocation allowed) ------------
__device__ float g_q [NA * D];   // relu(GN(actors @ Wq^T))
__device__ float g_qw[NA * D];   // g_q @ Wc0[:,128:256]^T
__device__ float g_cw[NN * D];   // nodes @ Wc0[:,256:384]^T
__device__ float g_a [NA * D];   // actors @ Wagt^T (+ scattered messages)
__device__ float g_x [NA * D];
__device__ float g_act[NA * D];

// ----------------------------- bf16 helpers ----------------------------------
__device__ __forceinline__ uint32_t pk(float e, float o) {
    uint32_t r;
    asm("cvt.rn.bf16x2.f32 %0, %1, %2;" : "=r"(r) : "f"(o), "f"(e));
    return r;  // lo16 = e (even k), hi16 = o (odd k)
}
__device__ __forceinline__ float lo16f(uint32_t p) { return __uint_as_float(p << 16); }
__device__ __forceinline__ float hi16f(uint32_t p) { return __uint_as_float(p & 0xffff0000u); }

__device__ __forceinline__ void mma16816(float& c0, float& c1, float& c2, float& c3,
                                         uint32_t a0, uint32_t a1, uint32_t a2, uint32_t a3,
                                         uint32_t b0, uint32_t b1) {
    asm volatile(
        "mma.sync.aligned.m16n8k16.row.col.f32.bf16.bf16.f32 "
        "{%0,%1,%2,%3}, {%4,%5,%6,%7}, {%8,%9}, {%0,%1,%2,%3};"
        : "+f"(c0), "+f"(c1), "+f"(c2), "+f"(c3)
        : "r"(a0), "r"(a1), "r"(a2), "r"(a3), "r"(b0), "r"(b1));
}

// stage one [128 x 128] fp32 weight chunk -> bf16 hi/lo pair buffers
__device__ __forceinline__ void stageB(const float* __restrict__ W, int rowlen,
                                       uint32_t* __restrict__ Bh,
                                       uint32_t* __restrict__ Bl) {
    const int t = threadIdx.x;
    const int n = t >> 1, kh = (t & 1) << 6;
    const float4* src = reinterpret_cast<const float4*>(W + n * rowlen + kh);
    const int pb = n * SA + ((t & 1) << 5);
#pragma unroll
    for (int i = 0; i < 16; i++) {
        float4 v = src[i];
        uint32_t h0 = pk(v.x, v.y), h1 = pk(v.z, v.w);
        Bh[pb + 2 * i]     = h0;
        Bh[pb + 2 * i + 1] = h1;
        Bl[pb + 2 * i]     = pk(v.x - lo16f(h0), v.y - hi16f(h0));
        Bl[pb + 2 * i + 1] = pk(v.z - lo16f(h1), v.w - hi16f(h1));
    }
}

// 3-term emulated fp32 GEMM: C[128 rows x 128 cols] += A[128x128] @ B^T
// warp (wM in 0..3, wN in 0..1): rows wM*32..+31 (2 m-tiles), cols wN*64..+63
__device__ __forceinline__ void do_gemm(
    const uint32_t* __restrict__ Ah, const uint32_t* __restrict__ Al,
    const uint32_t* __restrict__ Bh, const uint32_t* __restrict__ Bl,
    int wM, int wN, int g, int tq, float (&c)[2][8][4]) {
    const int ar0 = (wM * 32 + g) * SA + tq;
    const int ar1 = ar0 + 16 * SA;
    const int nb  = (wN * 64 + g) * SA + tq;
    for (int s = 0; s < 8; s++) {
        const int ks = 8 * s;
        uint32_t ah0[4], ah1[4], al0[4], al1[4];
        ah0[0] = Ah[ar0 + ks];          ah0[1] = Ah[ar0 + 8 * SA + ks];
        ah0[2] = Ah[ar0 + ks + 4];      ah0[3] = Ah[ar0 + 8 * SA + ks + 4];
        al0[0] = Al[ar0 + ks];          al0[1] = Al[ar0 + 8 * SA + ks];
        al0[2] = Al[ar0 + ks + 4];      al0[3] = Al[ar0 + 8 * SA + ks + 4];
        ah1[0] = Ah[ar1 + ks];          ah1[1] = Ah[ar1 + 8 * SA + ks];
        ah1[2] = Ah[ar1 + ks + 4];      ah1[3] = Ah[ar1 + 8 * SA + ks + 4];
        al1[0] = Al[ar1 + ks];          al1[1] = Al[ar1 + 8 * SA + ks];
        al1[2] = Al[ar1 + ks + 4];      al1[3] = Al[ar1 + 8 * SA + ks + 4];
#pragma unroll
        for (int nf = 0; nf < 8; nf++) {
            const int bo = nb + nf * 8 * SA + ks;
            uint32_t bh0 = Bh[bo], bh1 = Bh[bo + 4];
            uint32_t bl0 = Bl[bo], bl1 = Bl[bo + 4];
            mma16816(c[0][nf][0], c[0][nf][1], c[0][nf][2], c[0][nf][3],
                     al0[0], al0[1], al0[2], al0[3], bh0, bh1);
            mma16816(c[0][nf][0], c[0][nf][1], c[0][nf][2], c[0][nf][3],
                     ah0[0], ah0[1], ah0[2], ah0[3], bl0, bl1);
            mma16816(c[0][nf][0], c[0][nf][1], c[0][nf][2], c[0][nf][3],
                     ah0[0], ah0[1], ah0[2], ah0[3], bh0, bh1);
            mma16816(c[1][nf][0], c[1][nf][1], c[1][nf][2], c[1][nf][3],
                     al1[0], al1[1], al1[2], al1[3], bh0, bh1);
            mma16816(c[1][nf][0], c[1][nf][1], c[1][nf][2], c[1][nf][3],
                     ah1[0], ah1[1], ah1[2], ah1[3], bl0, bl1);
            mma16816(c[1][nf][0], c[1][nf][1], c[1][nf][2], c[1][nf][3],
                     ah1[0], ah1[1], ah1[2], ah1[3], bh0, bh1);
        }
    }
}

// GN(+relu) epilogue over C; writes normalized bf16 hi/lo back to A pairs 0..63
__device__ __forceinline__ void epi_gn(
    float (&c)[2][8][4], const float* __restrict__ sG, const float* __restrict__ sB,
    uint32_t* __restrict__ Ah, uint32_t* __restrict__ Al,
    float (*sSum)[MT], float (*sSq)[MT], int wM, int wN, int g, int tq) {
    float s_[2][2] = {{0, 0}, {0, 0}}, q_[2][2] = {{0, 0}, {0, 0}};
#pragma unroll
    for (int m = 0; m < 2; m++)
#pragma unroll
        for (int nf = 0; nf < 8; nf++) {
            float v0 = c[m][nf][0], v1 = c[m][nf][1];
            float v2 = c[m][nf][2], v3 = c[m][nf][3];
            s_[m][0] += v0 + v1;
            q_[m][0] = fmaf(v0, v0, fmaf(v1, v1, q_[m][0]));
            s_[m][1] += v2 + v3;
            q_[m][1] = fmaf(v2, v2, fmaf(v3, v3, q_[m][1]));
        }
#pragma unroll
    for (int m = 0; m < 2; m++)
#pragma unroll
        for (int h = 0; h < 2; h++) {
            s_[m][h] += __shfl_xor_sync(0xffffffffu, s_[m][h], 1);
            s_[m][h] += __shfl_xor_sync(0xffffffffu, s_[m][h], 2);
            q_[m][h] += __shfl_xor_sync(0xffffffffu, q_[m][h], 1);
            q_[m][h] += __shfl_xor_sync(0xffffffffu, q_[m][h], 2);
        }
    if (tq == 0) {
#pragma unroll
        for (int m = 0; m < 2; m++)
#pragma unroll
            for (int h = 0; h < 2; h++) {
                int row = wM * 32 + m * 16 + g + 8 * h;
                sSum[wN][row] = s_[m][h];
                sSq[wN][row]  = q_[m][h];
            }
    }
    __syncthreads();
    float mu[2][2], rs[2][2];
#pragma unroll
    for (int m = 0; m < 2; m++)
#pragma unroll
        for (int h = 0; h < 2; h++) {
            int row = wM * 32 + m * 16 + g + 8 * h;
            float S = sSum[0][row] + sSum[1][row];
            float Q = sSq[0][row] + sSq[1][row];
            mu[m][h] = S * (1.0f / 128.0f);
            rs[m][h] = rsqrtf(Q * (1.0f / 128.0f) - mu[m][h] * mu[m][h] + EPS);
        }
#pragma unroll
    for (int m = 0; m < 2; m++) {
        const int rb = wM * 32 + m * 16 + g;
#pragma unroll
        for (int nf = 0; nf < 8; nf++) {
            const int ch = wN * 64 + nf * 8 + 2 * tq;
            const float g0 = sG[ch], g1 = sG[ch + 1];
            const float b0 = sB[ch], b1 = sB[ch + 1];
            const int p = wN * 32 + nf * 4 + tq;
            float e = fmaxf((c[m][nf][0] - mu[m][0]) * rs[m][0] * g0 + b0, 0.0f);
            float o = fmaxf((c[m][nf][1] - mu[m][0]) * rs[m][0] * g1 + b1, 0.0f);
            uint32_t hp = pk(e, o);
            Ah[rb * SA + p] = hp;
            Al[rb * SA + p] = pk(e - lo16f(hp), o - hi16f(hp));
            e = fmaxf((c[m][nf][2] - mu[m][1]) * rs[m][1] * g0 + b0, 0.0f);
            o = fmaxf((c[m][nf][3] - mu[m][1]) * rs[m][1] * g1 + b1, 0.0f);
            hp = pk(e, o);
            Ah[(rb + 8) * SA + p] = hp;
            Al[(rb + 8) * SA + p] = pk(e - lo16f(hp), o - hi16f(hp));
        }
    }
}

// ============================ edge kernel (HMMA) =============================
// per 128-edge CTA:
//   h = relu(dist0(d2))                       (scalar)
//   d = relu(GN(h @ W1^T))                    (mma)
//   u = relu(GN(d @ Wc0d^T + qW[hi] + cW[wi]))(mma, gather-init accums)
//   m = u @ Wc1^T                             (mma) ; atomicAdd into g_a[hi]
__global__ void __launch_bounds__(256, 1) edge_mma_kernel(
    const float* __restrict__ actor_ctrs, const float* __restrict__ node_ctrs,
    const int* __restrict__ hi, const int* __restrict__ wi,
    const float* __restrict__ W0, const float* __restrict__ b0,
    const float* __restrict__ W1, const float* __restrict__ g1, const float* __restrict__ b1v,
    const float* __restrict__ Wc0d, const float* __restrict__ gc0, const float* __restrict__ bc0,
    const float* __restrict__ Wc1) {
    extern __shared__ uint32_t smu[];
    uint32_t* Ah = smu;
    uint32_t* Al = smu + 128 * SA;
    uint32_t* Bh = smu + 2 * 128 * SA;
    uint32_t* Bl = smu + 3 * 128 * SA;
    __shared__ float sW0[2 * D], sB0[D], sG1[D], sB1[D], sGc[D], sBc[D];
    __shared__ int sHi[MT], sWi[MT];
    __shared__ float sSum[2][MT], sSq[2][MT];

    const int tid = threadIdx.x;
    const int lane = tid & 31, wid = tid >> 5;
    const int wN = wid & 1, wM = wid >> 1;
    const int g = lane >> 2, tq = lane & 3;
    const int e0 = blockIdx.x * MT;

    sW0[tid] = W0[tid];
    if (tid < D) {
        sB0[tid] = b0[tid]; sG1[tid] = g1[tid]; sB1[tid] = b1v[tid];
        sGc[tid] = gc0[tid]; sBc[tid] = bc0[tid];
        sHi[tid] = hi[e0 + tid]; sWi[tid] = wi[e0 + tid];
    }
    __syncthreads();

    // ---- phase 0: h -> A pairs 0..63 ; stage B = W1 ----
    {
        const int row = tid >> 1, hf = tid & 1;
        const int h_ = sHi[row], w_ = sWi[row];
        float2 ac = reinterpret_cast<const float2*>(actor_ctrs)[h_];
        float2 nc = reinterpret_cast<const float2*>(node_ctrs)[w_];
        float dx = ac.x - nc.x, dy = ac.y - nc.y;
#pragma unroll
        for (int i = 0; i < 32; i++) {
            int ch = hf * 64 + 2 * i;
            float e = fmaxf(fmaf(dx, sW0[2 * ch],     fmaf(dy, sW0[2 * ch + 1], sB0[ch])),     0.0f);
            float o = fmaxf(fmaf(dx, sW0[2 * ch + 2], fmaf(dy, sW0[2 * ch + 3], sB0[ch + 1])), 0.0f);
            uint32_t hp = pk(e, o);
            Ah[row * SA + hf * 32 + i] = hp;
            Al[row * SA + hf * 32 + i] = pk(e - lo16f(hp), o - hi16f(hp));
        }
    }
    stageB(W1, 128, Bh, Bl);
    __syncthreads();

    float c[2][8][4];

    // ---- GEMM1: d_pre = h @ W1^T ----
#pragma unroll
    for (int m = 0; m < 2; m++)
#pragma unroll
        for (int nf = 0; nf < 8; nf++)
#pragma unroll
            for (int j = 0; j < 4; j++) c[m][nf][j] = 0.0f;
    do_gemm(Ah, Al, Bh, Bl, wM, wN, g, tq, c);
    epi_gn(c, sG1, sB1, Ah, Al, sSum, sSq, wM, wN, g, tq);   // d -> A
    stageB(Wc0d, 384, Bh, Bl);
    __syncthreads();

    // ---- GEMM2: u_pre = d @ Wc0d^T + qW[hi] + cW[wi] (gather-init) ----
#pragma unroll
    for (int m = 0; m < 2; m++)
#pragma unroll
        for (int h = 0; h < 2; h++) {
            int row = wM * 32 + m * 16 + g + 8 * h;
            const float2* qp = reinterpret_cast<const float2*>(
                g_qw + (size_t)sHi[row] * D + wN * 64);
            const float2* cp = reinterpret_cast<const float2*>(
                g_cw + (size_t)sWi[row] * D + wN * 64);
#pragma unroll
            for (int nf = 0; nf < 8; nf++) {
                float2 a_ = qp[nf * 4 + tq];
                float2 b_ = cp[nf * 4 + tq];
                c[m][nf][2 * h]     = a_.x + b_.x;
                c[m][nf][2 * h + 1] = a_.y + b_.y;
            }
        }
    do_gemm(Ah, Al, Bh, Bl, wM, wN, g, tq, c);
    epi_gn(c, sGc, sBc, Ah, Al, sSum, sSq, wM, wN, g, tq);   // u -> A
    stageB(Wc1, 128, Bh, Bl);
    __syncthreads();

    // ---- GEMM3: m = u @ Wc1^T ; scatter ----
#pragma unroll
    for (int m = 0; m < 2; m++)
#pragma unroll
        for (int nf = 0; nf < 8; nf++)
#pragma unroll
            for (int j = 0; j < 4; j++) c[m][nf][j] = 0.0f;
    do_gemm(Ah, Al, Bh, Bl, wM, wN, g, tq, c);
#pragma unroll
    for (int m = 0; m < 2; m++)
#pragma unroll
        for (int h = 0; h < 2; h++) {
            int row = wM * 32 + m * 16 + g + 8 * h;
            float* base = g_a + (size_t)sHi[row] * D + wN * 64;
#pragma unroll
            for (int nf = 0; nf < 8; nf++) {
                int ch = nf * 8 + 2 * tq;
                atomicAdd(base + ch,     c[m][nf][2 * h]);
                atomicAdd(base + ch + 1, c[m][nf][2 * h + 1]);
            }
        }
}

// ===================== fp32 actor-side kernels (R1-proven) ===================
template <int K, int SSTR, int WSTR>
__device__ __forceinline__ void tile_gemm(const float* __restrict__ W,
                                          const float* sIn, float* sOut,
                                          float* sW) {
    const int tid = threadIdx.x;
    const int jb = tid & 31, eb = tid >> 5;
    float acc[4][4];
#pragma unroll
    for (int i = 0; i < 4; i++)
#pragma unroll
        for (int j = 0; j < 4; j++) acc[i][j] = 0.0f;
    for (int k0 = 0; k0 < K; k0 += 32) {
        __syncthreads();
        {
            const int j = tid >> 1;
            const int kk0 = (tid & 1) << 4;
            const float4* Wr = reinterpret_cast<const float4*>(W + j * WSTR + k0 + kk0);
#pragma unroll
            for (int i = 0; i < 4; i++) {
                float4 v = Wr[i];
                int kk = kk0 + i * 4;
                sW[kk * 128 + j]       = v.x;
                sW[(kk + 1) * 128 + j] = v.y;
                sW[(kk + 2) * 128 + j] = v.z;
                sW[(kk + 3) * 128 + j] = v.w;
            }
        }
        __syncthreads();
#pragma unroll
        for (int kk = 0; kk < 32; kk += 4) {
            float4 a4[4];
#pragma unroll
            for (int i = 0; i < 4; i++)
                a4[i] = *reinterpret_cast<const float4*>(sIn + (eb * 4 + i) * SSTR + k0 + kk);
#pragma unroll
            for (int t = 0; t < 4; t++) {
                float4 bv = *reinterpret_cast<const float4*>(sW + (kk + t) * 128 + jb * 4);
#pragma unroll
                for (int i = 0; i < 4; i++) {
                    float av = (t == 0) ? a4[i].x : (t == 1) ? a4[i].y
                             : (t == 2) ? a4[i].z : a4[i].w;
                    acc[i][0] = fmaf(av, bv.x, acc[i][0]);
                    acc[i][1] = fmaf(av, bv.y, acc[i][1]);
                    acc[i][2] = fmaf(av, bv.z, acc[i][2]);
                    acc[i][3] = fmaf(av, bv.w, acc[i][3]);
                }
            }
        }
    }
    __syncthreads();
#pragma unroll
    for (int i = 0; i < 4; i++) {
        float4 v = make_float4(acc[i][0], acc[i][1], acc[i][2], acc[i][3]);
        *reinterpret_cast<float4*>(sOut + (eb * 4 + i) * 128 + jb * 4) = v;
    }
}

template <bool GN, bool RELU, bool RES, int WSTR>
__global__ void __launch_bounds__(256) rowgemm_kernel(
    const float* __restrict__ in, const float* __restrict__ W,
    const float* __restrict__ g, const float* __restrict__ bb,
    const float* __restrict__ res, float* __restrict__ out) {
    __shared__ float sIn[TILE * 128];
    __shared__ float sWO[32 * 128];
    const int tid = threadIdx.x;
    const int r0 = blockIdx.x * TILE;
    {
        const int r = tid >> 3, seg = tid & 7;
        const float4* src = reinterpret_cast<const float4*>(in + (size_t)(r0 + r) * D) + seg * 4;
        float4* dst = reinterpret_cast<float4*>(sIn + r * 128) + seg * 4;
#pragma unroll
        for (int i = 0; i < 4; i++) dst[i] = src[i];
    }
    __syncthreads();
    tile_gemm<128, 128, WSTR>(W, sIn, sWO, sWO);
    __syncthreads();
    if (GN) {
        const int warp = tid >> 5, lane = tid & 31;
        const float gg0 = g[lane], gg1 = g[lane + 32], gg2 = g[lane + 64], gg3 = g[lane + 96];
        const float bb0 = bb[lane], bb1 = bb[lane + 32], bb2 = bb[lane + 64], bb3 = bb[lane + 96];
        for (int e = warp; e < TILE; e += 8) {
            float v0 = sWO[e * 128 + lane];
            float v1 = sWO[e * 128 + lane + 32];
            float v2 = sWO[e * 128 + lane + 64];
            float v3 = sWO[e * 128 + lane + 96];
            float s = v0 + v1 + v2 + v3;
            float q = fmaf(v0, v0, fmaf(v1, v1, fmaf(v2, v2, v3 * v3)));
#pragma unroll
            for (int o = 16; o > 0; o >>= 1) {
                s += __shfl_xor_sync(0xffffffffu, s, o);
                q += __shfl_xor_sync(0xffffffffu, q, o);
            }
            float mu = s * (1.0f / 128.0f);
            float rs = rsqrtf(q * (1.0f / 128.0f) - mu * mu + EPS);
            float y0 = (v0 - mu) * rs * gg0 + bb0;
            float y1 = (v1 - mu) * rs * gg1 + bb1;
            float y2 = (v2 - mu) * rs * gg2 + bb2;
            float y3 = (v3 - mu) * rs * gg3 + bb3;
            const size_t rb = (size_t)(r0 + e) * D;
            if (RES) {
                y0 += res[rb + lane];      y1 += res[rb + lane + 32];
                y2 += res[rb + lane + 64]; y3 += res[rb + lane + 96];
            }
            if (RELU) {
                y0 = fmaxf(y0, 0.0f); y1 = fmaxf(y1, 0.0f);
                y2 = fmaxf(y2, 0.0f); y3 = fmaxf(y3, 0.0f);
            }
            out[rb + lane]      = y0;
            out[rb + lane + 32] = y1;
            out[rb + lane + 64] = y2;
            out[rb + lane + 96] = y3;
        }
    } else {
        const int r = tid >> 3, seg = tid & 7;
        float4* dst = reinterpret_cast<float4*>(out + (size_t)(r0 + r) * D) + seg * 4;
        const float4* src = reinterpret_cast<const float4*>(sWO + r * 128) + seg * 4;
#pragma unroll
        for (int i = 0; i < 4; i++) dst[i] = src[i];
    }
}

__global__ void __launch_bounds__(256) gnrows_kernel(
    const float* __restrict__ in, const float* __restrict__ g,
    const float* __restrict__ bb, float* __restrict__ out) {
    const int lane = threadIdx.x & 31;
    const int row = blockIdx.x * 8 + (threadIdx.x >> 5);
    const float* x = in + (size_t)row * D;
    float v0 = x[lane], v1 = x[lane + 32], v2 = x[lane + 64], v3 = x[lane + 96];
    float s = v0 + v1 + v2 + v3;
    float q = fmaf(v0, v0, fmaf(v1, v1, fmaf(v2, v2, v3 * v3)));
#pragma unroll
    for (int o = 16; o > 0; o >>= 1) {
        s += __shfl_xor_sync(0xffffffffu, s, o);
        q += __shfl_xor_sync(0xffffffffu, q, o);
    }
    float mu = s * (1.0f / 128.0f);
    float rs = rsqrtf(q * (1.0f / 128.0f) - mu * mu + EPS);
    float* o_ = out + (size_t)row * D;
    o_[lane]      = fmaxf((v0 - mu) * rs * g[lane] + bb[lane], 0.0f);
    o_[lane + 32] = fmaxf((v1 - mu) * rs * g[lane + 32] + bb[lane + 32], 0.0f);
    o_[lane + 64] = fmaxf((v2 - mu) * rs * g[lane + 64] + bb[lane + 64], 0.0f);
    o_[lane + 96] = fmaxf((v3 - mu) * rs * g[lane + 96] + bb[lane + 96], 0.0f);
}

#define EDGE_SMEM (4 * 128 * SA * 4)

extern "C" void kernel_launch(void* const* d_in, const int* in_sizes, int n_in,
                              void* d_out, int out_size) {
    (void)in_sizes; (void)n_in; (void)out_size;
    const float* actors     = (const float*)d_in[0];
    const float* nodes      = (const float*)d_in[1];
    const float* actor_ctrs = (const float*)d_in[2];
    const float* node_ctrs  = (const float*)d_in[3];
    const int*   hi         = (const int*)d_in[4];
    const int*   wi         = (const int*)d_in[5];
    const float* dist0_W = (const float*)d_in[6];
    const float* dist0_b = (const float*)d_in[7];
    const float* dist1_W = (const float*)d_in[8];
    const float* dist1_g = (const float*)d_in[9];
    const float* dist1_b = (const float*)d_in[10];
    const float* query_W = (const float*)d_in[11];
    const float* query_g = (const float*)d_in[12];
    const float* query_b = (const float*)d_in[13];
    const float* ctx0_W  = (const float*)d_in[14];
    const float* ctx0_g  = (const float*)d_in[15];
    const float* ctx0_b  = (const float*)d_in[16];
    const float* ctx1_W  = (const float*)d_in[17];
    const float* agt_W   = (const float*)d_in[18];
    const float* norm_g  = (const float*)d_in[19];
    const float* norm_b  = (const float*)d_in[20];
    const float* lin_W   = (const float*)d_in[21];
    const float* lin_g   = (const float*)d_in[22];
    const float* lin_b   = (const float*)d_in[23];
    float* outp = (float*)d_out;

    void *pq_, *pqw_, *pcw_, *pa_, *px_, *pact_;
    cudaGetSymbolAddress(&pq_, g_q);
    cudaGetSymbolAddress(&pqw_, g_qw);
    cudaGetSymbolAddress(&pcw_, g_cw);
    cudaGetSymbolAddress(&pa_, g_a);
    cudaGetSymbolAddress(&px_, g_x);
    cudaGetSymbolAddress(&pact_, g_act);
    float* p_q   = (float*)pq_;
    float* p_qw  = (float*)pqw_;
    float* p_cw  = (float*)pcw_;
    float* p_a   = (float*)pa_;
    float* p_x   = (float*)px_;
    float* p_act = (float*)pact_;

    cudaFuncSetAttribute(edge_mma_kernel,
                         cudaFuncAttributeMaxDynamicSharedMemorySize, EDGE_SMEM);

    const int DD = D * D;
    for (int i = 0; i < NB; i++) {
        const float* cur = (i == 0) ? actors : p_act;
        float* nxt = (i == NB - 1) ? outp : p_act;
        const float* Wc0 = ctx0_W + (size_t)i * D * 3 * D;

        // q = relu(GN(actors @ Wq^T))
        rowgemm_kernel<true, true, false, 128><<<NA / TILE, 256>>>(
            cur, query_W + i * DD, query_g + i * D, query_b + i * D, nullptr, p_q);
        // qW = q @ Wc0[:,128:256]^T
        rowgemm_kernel<false, false, false, 384><<<NA / TILE, 256>>>(
            p_q, Wc0 + 128, nullptr, nullptr, nullptr, p_qw);
        // cW = nodes @ Wc0[:,256:384]^T
        rowgemm_kernel<false, false, false, 384><<<NN / TILE, 256>>>(
            nodes, Wc0 + 256, nullptr, nullptr, nullptr, p_cw);
        // a = actors @ Wagt^T
        rowgemm_kernel<false, false, false, 128><<<NA / TILE, 256>>>(
            cur, agt_W + i * DD, nullptr, nullptr, nullptr, p_a);
        // fused edge chain (HMMA) + scatter into a
        edge_mma_kernel<<<NE / MT, 256, EDGE_SMEM>>>(
            actor_ctrs, node_ctrs, hi, wi,
            dist0_W + i * D * 2, dist0_b + i * D,
            dist1_W + i * DD, dist1_g + i * D, dist1_b + i * D,
            Wc0, ctx0_g + i * D, ctx0_b + i * D,
            ctx1_W + i * DD);
        // x = relu(GN(a))
        gnrows_kernel<<<NA / 8, 256>>>(p_a, norm_g + i * D, norm_b + i * D, p_x);
        // out = relu(GN(x @ Wlin^T) + res)
        rowgemm_kernel<true, true, true, 128><<<NA / TILE, 256>>>(
            p_x, lin_W + i * DD, lin_g + i * D, lin_b + i * D, cur, nxt);
    }
}

// round 6
// speedup vs baseline: 3.3040x; 1.0899x over previous
#include <cuda_runtime.h>
#include <cstdint>

#define NA 8192
#define NN 65536
#define NE 262144
#define D  128
#define NB 2
#define MT  128          // rows per HMMA CTA
#define SA  68           // smem pair stride (64 pairs + 4 pad -> conflict-free)
#define EPS 1e-5f

// ---------------- scratch (device globals; no allocation allowed) ------------
__device__ float g_q [NA * D];   // relu(GN(actors @ Wq^T))
__device__ float g_qw[NA * D];   // g_q @ Wc0[:,128:256]^T
__device__ float g_cw[NN * D];   // nodes @ Wc0[:,256:384]^T
__device__ float g_a [NA * D];   // actors @ Wagt^T (+ scattered messages)
__device__ float g_x [NA * D];
__device__ float g_act[NA * D];

// ----------------------------- bf16 helpers ----------------------------------
__device__ __forceinline__ uint32_t pk(float e, float o) {
    uint32_t r;
    asm("cvt.rn.bf16x2.f32 %0, %1, %2;" : "=r"(r) : "f"(o), "f"(e));
    return r;  // lo16 = e (even k), hi16 = o (odd k)
}
__device__ __forceinline__ float lo16f(uint32_t p) { return __uint_as_float(p << 16); }
__device__ __forceinline__ float hi16f(uint32_t p) { return __uint_as_float(p & 0xffff0000u); }

__device__ __forceinline__ void mma16816(float& c0, float& c1, float& c2, float& c3,
                                         uint32_t a0, uint32_t a1, uint32_t a2, uint32_t a3,
                                         uint32_t b0, uint32_t b1) {
    asm volatile(
        "mma.sync.aligned.m16n8k16.row.col.f32.bf16.bf16.f32 "
        "{%0,%1,%2,%3}, {%4,%5,%6,%7}, {%8,%9}, {%0,%1,%2,%3};"
        : "+f"(c0), "+f"(c1), "+f"(c2), "+f"(c3)
        : "r"(a0), "r"(a1), "r"(a2), "r"(a3), "r"(b0), "r"(b1));
}

// stage one [128 x 128] fp32 matrix chunk -> bf16 hi/lo pair buffers
__device__ __forceinline__ void stageB(const float* __restrict__ W, int rowlen,
                                       uint32_t* __restrict__ Bh,
                                       uint32_t* __restrict__ Bl) {
    const int t = threadIdx.x;
    const int n = t >> 1, kh = (t & 1) << 6;
    const float4* src = reinterpret_cast<const float4*>(W + (size_t)n * rowlen + kh);
    const int pb = n * SA + ((t & 1) << 5);
#pragma unroll
    for (int i = 0; i < 16; i++) {
        float4 v = src[i];
        uint32_t h0 = pk(v.x, v.y), h1 = pk(v.z, v.w);
        Bh[pb + 2 * i]     = h0;
        Bh[pb + 2 * i + 1] = h1;
        Bl[pb + 2 * i]     = pk(v.x - lo16f(h0), v.y - hi16f(h0));
        Bl[pb + 2 * i + 1] = pk(v.z - lo16f(h1), v.w - hi16f(h1));
    }
}

// 3-term emulated fp32 GEMM: C[128 rows x 128 cols] += A[128x128] @ B^T
__device__ __forceinline__ void do_gemm(
    const uint32_t* __restrict__ Ah, const uint32_t* __restrict__ Al,
    const uint32_t* __restrict__ Bh, const uint32_t* __restrict__ Bl,
    int wM, int wN, int g, int tq, float (&c)[2][8][4]) {
    const int ar0 = (wM * 32 + g) * SA + tq;
    const int ar1 = ar0 + 16 * SA;
    const int nb  = (wN * 64 + g) * SA + tq;
    for (int s = 0; s < 8; s++) {
        const int ks = 8 * s;
        uint32_t ah0[4], ah1[4], al0[4], al1[4];
        ah0[0] = Ah[ar0 + ks];          ah0[1] = Ah[ar0 + 8 * SA + ks];
        ah0[2] = Ah[ar0 + ks + 4];      ah0[3] = Ah[ar0 + 8 * SA + ks + 4];
        al0[0] = Al[ar0 + ks];          al0[1] = Al[ar0 + 8 * SA + ks];
        al0[2] = Al[ar0 + ks + 4];      al0[3] = Al[ar0 + 8 * SA + ks + 4];
        ah1[0] = Ah[ar1 + ks];          ah1[1] = Ah[ar1 + 8 * SA + ks];
        ah1[2] = Ah[ar1 + ks + 4];      ah1[3] = Ah[ar1 + 8 * SA + ks + 4];
        al1[0] = Al[ar1 + ks];          al1[1] = Al[ar1 + 8 * SA + ks];
        al1[2] = Al[ar1 + ks + 4];      al1[3] = Al[ar1 + 8 * SA + ks + 4];
#pragma unroll
        for (int nf = 0; nf < 8; nf++) {
            const int bo = nb + nf * 8 * SA + ks;
            uint32_t bh0 = Bh[bo], bh1 = Bh[bo + 4];
            uint32_t bl0 = Bl[bo], bl1 = Bl[bo + 4];
            mma16816(c[0][nf][0], c[0][nf][1], c[0][nf][2], c[0][nf][3],
                     al0[0], al0[1], al0[2], al0[3], bh0, bh1);
            mma16816(c[0][nf][0], c[0][nf][1], c[0][nf][2], c[0][nf][3],
                     ah0[0], ah0[1], ah0[2], ah0[3], bl0, bl1);
            mma16816(c[0][nf][0], c[0][nf][1], c[0][nf][2], c[0][nf][3],
                     ah0[0], ah0[1], ah0[2], ah0[3], bh0, bh1);
            mma16816(c[1][nf][0], c[1][nf][1], c[1][nf][2], c[1][nf][3],
                     al1[0], al1[1], al1[2], al1[3], bh0, bh1);
            mma16816(c[1][nf][0], c[1][nf][1], c[1][nf][2], c[1][nf][3],
                     ah1[0], ah1[1], ah1[2], ah1[3], bl0, bl1);
            mma16816(c[1][nf][0], c[1][nf][1], c[1][nf][2], c[1][nf][3],
                     ah1[0], ah1[1], ah1[2], ah1[3], bh0, bh1);
        }
    }
}

// GN(+relu) epilogue over C; writes normalized bf16 hi/lo back to A pairs 0..63
__device__ __forceinline__ void epi_gn(
    float (&c)[2][8][4], const float* __restrict__ sG, const float* __restrict__ sB,
    uint32_t* __restrict__ Ah, uint32_t* __restrict__ Al,
    float (*sSum)[MT], float (*sSq)[MT], int wM, int wN, int g, int tq) {
    float s_[2][2] = {{0, 0}, {0, 0}}, q_[2][2] = {{0, 0}, {0, 0}};
#pragma unroll
    for (int m = 0; m < 2; m++)
#pragma unroll
        for (int nf = 0; nf < 8; nf++) {
            float v0 = c[m][nf][0], v1 = c[m][nf][1];
            float v2 = c[m][nf][2], v3 = c[m][nf][3];
            s_[m][0] += v0 + v1;
            q_[m][0] = fmaf(v0, v0, fmaf(v1, v1, q_[m][0]));
            s_[m][1] += v2 + v3;
            q_[m][1] = fmaf(v2, v2, fmaf(v3, v3, q_[m][1]));
        }
#pragma unroll
    for (int m = 0; m < 2; m++)
#pragma unroll
        for (int h = 0; h < 2; h++) {
            s_[m][h] += __shfl_xor_sync(0xffffffffu, s_[m][h], 1);
            s_[m][h] += __shfl_xor_sync(0xffffffffu, s_[m][h], 2);
            q_[m][h] += __shfl_xor_sync(0xffffffffu, q_[m][h], 1);
            q_[m][h] += __shfl_xor_sync(0xffffffffu, q_[m][h], 2);
        }
    if (tq == 0) {
#pragma unroll
        for (int m = 0; m < 2; m++)
#pragma unroll
            for (int h = 0; h < 2; h++) {
                int row = wM * 32 + m * 16 + g + 8 * h;
                sSum[wN][row] = s_[m][h];
                sSq[wN][row]  = q_[m][h];
            }
    }
    __syncthreads();
    float mu[2][2], rs[2][2];
#pragma unroll
    for (int m = 0; m < 2; m++)
#pragma unroll
        for (int h = 0; h < 2; h++) {
            int row = wM * 32 + m * 16 + g + 8 * h;
            float S = sSum[0][row] + sSum[1][row];
            float Q = sSq[0][row] + sSq[1][row];
            mu[m][h] = S * (1.0f / 128.0f);
            rs[m][h] = rsqrtf(Q * (1.0f / 128.0f) - mu[m][h] * mu[m][h] + EPS);
        }
#pragma unroll
    for (int m = 0; m < 2; m++) {
        const int rb = wM * 32 + m * 16 + g;
#pragma unroll
        for (int nf = 0; nf < 8; nf++) {
            const int ch = wN * 64 + nf * 8 + 2 * tq;
            const float g0 = sG[ch], g1 = sG[ch + 1];
            const float b0 = sB[ch], b1 = sB[ch + 1];
            const int p = wN * 32 + nf * 4 + tq;
            float e = fmaxf((c[m][nf][0] - mu[m][0]) * rs[m][0] * g0 + b0, 0.0f);
            float o = fmaxf((c[m][nf][1] - mu[m][0]) * rs[m][0] * g1 + b1, 0.0f);
            uint32_t hp = pk(e, o);
            Ah[rb * SA + p] = hp;
            Al[rb * SA + p] = pk(e - lo16f(hp), o - hi16f(hp));
            e = fmaxf((c[m][nf][2] - mu[m][1]) * rs[m][1] * g0 + b0, 0.0f);
            o = fmaxf((c[m][nf][3] - mu[m][1]) * rs[m][1] * g1 + b1, 0.0f);
            hp = pk(e, o);
            Ah[(rb + 8) * SA + p] = hp;
            Al[(rb + 8) * SA + p] = pk(e - lo16f(hp), o - hi16f(hp));
        }
    }
}

// ============================ edge kernel (HMMA) =============================
__global__ void __launch_bounds__(256, 1) edge_mma_kernel(
    const float* __restrict__ actor_ctrs, const float* __restrict__ node_ctrs,
    const int* __restrict__ hi, const int* __restrict__ wi,
    const float* __restrict__ W0, const float* __restrict__ b0,
    const float* __restrict__ W1, const float* __restrict__ g1, const float* __restrict__ b1v,
    const float* __restrict__ Wc0d, const float* __restrict__ gc0, const float* __restrict__ bc0,
    const float* __restrict__ Wc1) {
    extern __shared__ uint32_t smu[];
    uint32_t* Ah = smu;
    uint32_t* Al = smu + 128 * SA;
    uint32_t* Bh = smu + 2 * 128 * SA;
    uint32_t* Bl = smu + 3 * 128 * SA;
    __shared__ float sW0[2 * D], sB0[D], sG1[D], sB1[D], sGc[D], sBc[D];
    __shared__ int sHi[MT], sWi[MT];
    __shared__ float sSum[2][MT], sSq[2][MT];

    const int tid = threadIdx.x;
    const int lane = tid & 31, wid = tid >> 5;
    const int wN = wid & 1, wM = wid >> 1;
    const int g = lane >> 2, tq = lane & 3;
    const int e0 = blockIdx.x * MT;

    sW0[tid] = W0[tid];
    if (tid < D) {
        sB0[tid] = b0[tid]; sG1[tid] = g1[tid]; sB1[tid] = b1v[tid];
        sGc[tid] = gc0[tid]; sBc[tid] = bc0[tid];
        sHi[tid] = hi[e0 + tid]; sWi[tid] = wi[e0 + tid];
    }
    __syncthreads();

    // ---- phase 0: h -> A pairs 0..63 ; stage B = W1 ----
    {
        const int row = tid >> 1, hf = tid & 1;
        const int h_ = sHi[row], w_ = sWi[row];
        float2 ac = reinterpret_cast<const float2*>(actor_ctrs)[h_];
        float2 nc = reinterpret_cast<const float2*>(node_ctrs)[w_];
        float dx = ac.x - nc.x, dy = ac.y - nc.y;
#pragma unroll
        for (int i = 0; i < 32; i++) {
            int ch = hf * 64 + 2 * i;
            float e = fmaxf(fmaf(dx, sW0[2 * ch],     fmaf(dy, sW0[2 * ch + 1], sB0[ch])),     0.0f);
            float o = fmaxf(fmaf(dx, sW0[2 * ch + 2], fmaf(dy, sW0[2 * ch + 3], sB0[ch + 1])), 0.0f);
            uint32_t hp = pk(e, o);
            Ah[row * SA + hf * 32 + i] = hp;
            Al[row * SA + hf * 32 + i] = pk(e - lo16f(hp), o - hi16f(hp));
        }
    }
    stageB(W1, 128, Bh, Bl);
    __syncthreads();

    float c[2][8][4];

    // ---- GEMM1: d_pre = h @ W1^T ----
#pragma unroll
    for (int m = 0; m < 2; m++)
#pragma unroll
        for (int nf = 0; nf < 8; nf++)
#pragma unroll
            for (int j = 0; j < 4; j++) c[m][nf][j] = 0.0f;
    do_gemm(Ah, Al, Bh, Bl, wM, wN, g, tq, c);
    epi_gn(c, sG1, sB1, Ah, Al, sSum, sSq, wM, wN, g, tq);
    stageB(Wc0d, 384, Bh, Bl);
    __syncthreads();

    // ---- GEMM2: u_pre = d @ Wc0d^T + qW[hi] + cW[wi] ----
#pragma unroll
    for (int m = 0; m < 2; m++)
#pragma unroll
        for (int h = 0; h < 2; h++) {
            int row = wM * 32 + m * 16 + g + 8 * h;
            const float2* qp = reinterpret_cast<const float2*>(
                g_qw + (size_t)sHi[row] * D + wN * 64);
            const float2* cp = reinterpret_cast<const float2*>(
                g_cw + (size_t)sWi[row] * D + wN * 64);
#pragma unroll
            for (int nf = 0; nf < 8; nf++) {
                float2 a_ = qp[nf * 4 + tq];
                float2 b_ = cp[nf * 4 + tq];
                c[m][nf][2 * h]     = a_.x + b_.x;
                c[m][nf][2 * h + 1] = a_.y + b_.y;
            }
        }
    do_gemm(Ah, Al, Bh, Bl, wM, wN, g, tq, c);
    epi_gn(c, sGc, sBc, Ah, Al, sSum, sSq, wM, wN, g, tq);
    stageB(Wc1, 128, Bh, Bl);
    __syncthreads();

    // ---- GEMM3: m = u @ Wc1^T ; scatter ----
#pragma unroll
    for (int m = 0; m < 2; m++)
#pragma unroll
        for (int nf = 0; nf < 8; nf++)
#pragma unroll
            for (int j = 0; j < 4; j++) c[m][nf][j] = 0.0f;
    do_gemm(Ah, Al, Bh, Bl, wM, wN, g, tq, c);
#pragma unroll
    for (int m = 0; m < 2; m++)
#pragma unroll
        for (int h = 0; h < 2; h++) {
            int row = wM * 32 + m * 16 + g + 8 * h;
            float* base = g_a + (size_t)sHi[row] * D + wN * 64;
#pragma unroll
            for (int nf = 0; nf < 8; nf++) {
                int ch = nf * 8 + 2 * tq;
                atomicAdd(base + ch,     c[m][nf][2 * h]);
                atomicAdd(base + ch + 1, c[m][nf][2 * h + 1]);
            }
        }
}

// ================= HMMA row-GEMM: out[128,128] = f(in @ W^T) =================
// GN: GroupNorm epilogue; RELU; RES: add residual (res) before relu.
template <bool GN, bool RELU, bool RES>
__global__ void __launch_bounds__(256, 1) hgemm_kernel(
    const float* __restrict__ in, const float* __restrict__ W, int wstride,
    const float* __restrict__ gw, const float* __restrict__ bw,
    const float* __restrict__ res, float* __restrict__ out) {
    extern __shared__ uint32_t smu[];
    uint32_t* Ah = smu;
    uint32_t* Al = smu + 128 * SA;
    uint32_t* Bh = smu + 2 * 128 * SA;
    uint32_t* Bl = smu + 3 * 128 * SA;
    __shared__ float sG[D], sB[D];
    __shared__ float sSum[2][MT], sSq[2][MT];

    const int tid = threadIdx.x;
    const int lane = tid & 31, wid = tid >> 5;
    const int wN = wid & 1, wM = wid >> 1;
    const int g = lane >> 2, tq = lane & 3;
    const size_t r0 = (size_t)blockIdx.x * MT;

    if (GN && tid < D) { sG[tid] = gw[tid]; sB[tid] = bw[tid]; }
    stageB(in + r0 * D, 128, Ah, Al);
    stageB(W, wstride, Bh, Bl);
    __syncthreads();

    float c[2][8][4];
#pragma unroll
    for (int m = 0; m < 2; m++)
#pragma unroll
        for (int nf = 0; nf < 8; nf++)
#pragma unroll
            for (int j = 0; j < 4; j++) c[m][nf][j] = 0.0f;
    do_gemm(Ah, Al, Bh, Bl, wM, wN, g, tq, c);

    if (GN) {
        float s_[2][2] = {{0, 0}, {0, 0}}, q_[2][2] = {{0, 0}, {0, 0}};
#pragma unroll
        for (int m = 0; m < 2; m++)
#pragma unroll
            for (int nf = 0; nf < 8; nf++) {
                float v0 = c[m][nf][0], v1 = c[m][nf][1];
                float v2 = c[m][nf][2], v3 = c[m][nf][3];
                s_[m][0] += v0 + v1;
                q_[m][0] = fmaf(v0, v0, fmaf(v1, v1, q_[m][0]));
                s_[m][1] += v2 + v3;
                q_[m][1] = fmaf(v2, v2, fmaf(v3, v3, q_[m][1]));
            }
#pragma unroll
        for (int m = 0; m < 2; m++)
#pragma unroll
            for (int h = 0; h < 2; h++) {
                s_[m][h] += __shfl_xor_sync(0xffffffffu, s_[m][h], 1);
                s_[m][h] += __shfl_xor_sync(0xffffffffu, s_[m][h], 2);
                q_[m][h] += __shfl_xor_sync(0xffffffffu, q_[m][h], 1);
                q_[m][h] += __shfl_xor_sync(0xffffffffu, q_[m][h], 2);
            }
        if (tq == 0) {
#pragma unroll
            for (int m = 0; m < 2; m++)
#pragma unroll
                for (int h = 0; h < 2; h++) {
                    int row = wM * 32 + m * 16 + g + 8 * h;
                    sSum[wN][row] = s_[m][h];
                    sSq[wN][row]  = q_[m][h];
                }
        }
        __syncthreads();
#pragma unroll
        for (int m = 0; m < 2; m++)
#pragma unroll
            for (int h = 0; h < 2; h++) {
                int row = wM * 32 + m * 16 + g + 8 * h;
                float S = sSum[0][row] + sSum[1][row];
                float Q = sSq[0][row] + sSq[1][row];
                float mu = S * (1.0f / 128.0f);
                float rs = rsqrtf(Q * (1.0f / 128.0f) - mu * mu + EPS);
                float* op = out + (r0 + row) * D;
                const float* rp = RES ? res + (r0 + row) * D : nullptr;
#pragma unroll
                for (int nf = 0; nf < 8; nf++) {
                    int ch = wN * 64 + nf * 8 + 2 * tq;
                    float y0 = (c[m][nf][2 * h]     - mu) * rs * sG[ch]     + sB[ch];
                    float y1 = (c[m][nf][2 * h + 1] - mu) * rs * sG[ch + 1] + sB[ch + 1];
                    if (RES) { y0 += rp[ch]; y1 += rp[ch + 1]; }
                    if (RELU) { y0 = fmaxf(y0, 0.0f); y1 = fmaxf(y1, 0.0f); }
                    *reinterpret_cast<float2*>(op + ch) = make_float2(y0, y1);
                }
            }
    } else {
#pragma unroll
        for (int m = 0; m < 2; m++)
#pragma unroll
            for (int h = 0; h < 2; h++) {
                int row = wM * 32 + m * 16 + g + 8 * h;
                float* op = out + (r0 + row) * D;
#pragma unroll
                for (int nf = 0; nf < 8; nf++) {
                    int ch = wN * 64 + nf * 8 + 2 * tq;
                    float y0 = c[m][nf][2 * h], y1 = c[m][nf][2 * h + 1];
                    if (RELU) { y0 = fmaxf(y0, 0.0f); y1 = fmaxf(y1, 0.0f); }
                    *reinterpret_cast<float2*>(op + ch) = make_float2(y0, y1);
                }
            }
    }
}

// x = relu(GN(a)) ; one warp per row
__global__ void __launch_bounds__(256) gnrows_kernel(
    const float* __restrict__ in, const float* __restrict__ g,
    const float* __restrict__ bb, float* __restrict__ out) {
    const int lane = threadIdx.x & 31;
    const int row = blockIdx.x * 8 + (threadIdx.x >> 5);
    const float* x = in + (size_t)row * D;
    float v0 = x[lane], v1 = x[lane + 32], v2 = x[lane + 64], v3 = x[lane + 96];
    float s = v0 + v1 + v2 + v3;
    float q = fmaf(v0, v0, fmaf(v1, v1, fmaf(v2, v2, v3 * v3)));
#pragma unroll
    for (int o = 16; o > 0; o >>= 1) {
        s += __shfl_xor_sync(0xffffffffu, s, o);
        q += __shfl_xor_sync(0xffffffffu, q, o);
    }
    float mu = s * (1.0f / 128.0f);
    float rs = rsqrtf(q * (1.0f / 128.0f) - mu * mu + EPS);
    float* o_ = out + (size_t)row * D;
    o_[lane]      = fmaxf((v0 - mu) * rs * g[lane] + bb[lane], 0.0f);
    o_[lane + 32] = fmaxf((v1 - mu) * rs * g[lane + 32] + bb[lane + 32], 0.0f);
    o_[lane + 64] = fmaxf((v2 - mu) * rs * g[lane + 64] + bb[lane + 64], 0.0f);
    o_[lane + 96] = fmaxf((v3 - mu) * rs * g[lane + 96] + bb[lane + 96], 0.0f);
}

#define EDGE_SMEM (4 * 128 * SA * 4)

extern "C" void kernel_launch(void* const* d_in, const int* in_sizes, int n_in,
                              void* d_out, int out_size) {
    (void)in_sizes; (void)n_in; (void)out_size;
    const float* actors     = (const float*)d_in[0];
    const float* nodes      = (const float*)d_in[1];
    const float* actor_ctrs = (const float*)d_in[2];
    const float* node_ctrs  = (const float*)d_in[3];
    const int*   hi         = (const int*)d_in[4];
    const int*   wi         = (const int*)d_in[5];
    const float* dist0_W = (const float*)d_in[6];
    const float* dist0_b = (const float*)d_in[7];
    const float* dist1_W = (const float*)d_in[8];
    const float* dist1_g = (const float*)d_in[9];
    const float* dist1_b = (const float*)d_in[10];
    const float* query_W = (const float*)d_in[11];
    const float* query_g = (const float*)d_in[12];
    const float* query_b = (const float*)d_in[13];
    const float* ctx0_W  = (const float*)d_in[14];
    const float* ctx0_g  = (const float*)d_in[15];
    const float* ctx0_b  = (const float*)d_in[16];
    const float* ctx1_W  = (const float*)d_in[17];
    const float* agt_W   = (const float*)d_in[18];
    const float* norm_g  = (const float*)d_in[19];
    const float* norm_b  = (const float*)d_in[20];
    const float* lin_W   = (const float*)d_in[21];
    const float* lin_g   = (const float*)d_in[22];
    const float* lin_b   = (const float*)d_in[23];
    float* outp = (float*)d_out;

    void *pq_, *pqw_, *pcw_, *pa_, *px_, *pact_;
    cudaGetSymbolAddress(&pq_, g_q);
    cudaGetSymbolAddress(&pqw_, g_qw);
    cudaGetSymbolAddress(&pcw_, g_cw);
    cudaGetSymbolAddress(&pa_, g_a);
    cudaGetSymbolAddress(&px_, g_x);
    cudaGetSymbolAddress(&pact_, g_act);
    float* p_q   = (float*)pq_;
    float* p_qw  = (float*)pqw_;
    float* p_cw  = (float*)pcw_;
    float* p_a   = (float*)pa_;
    float* p_x   = (float*)px_;
    float* p_act = (float*)pact_;

    cudaFuncSetAttribute(edge_mma_kernel,
                         cudaFuncAttributeMaxDynamicSharedMemorySize, EDGE_SMEM);
    cudaFuncSetAttribute(hgemm_kernel<true, true, false>,
                         cudaFuncAttributeMaxDynamicSharedMemorySize, EDGE_SMEM);
    cudaFuncSetAttribute(hgemm_kernel<false, false, false>,
                         cudaFuncAttributeMaxDynamicSharedMemorySize, EDGE_SMEM);
    cudaFuncSetAttribute(hgemm_kernel<true, true, true>,
                         cudaFuncAttributeMaxDynamicSharedMemorySize, EDGE_SMEM);

    const int DD = D * D;
    for (int i = 0; i < NB; i++) {
        const float* cur = (i == 0) ? actors : p_act;
        float* nxt = (i == NB - 1) ? outp : p_act;
        const float* Wc0 = ctx0_W + (size_t)i * D * 3 * D;

        // q = relu(GN(actors @ Wq^T))
        hgemm_kernel<true, true, false><<<NA / MT, 256, EDGE_SMEM>>>(
            cur, query_W + i * DD, 128, query_g + i * D, query_b + i * D, nullptr, p_q);
        // qW = q @ Wc0[:,128:256]^T
        hgemm_kernel<false, false, false><<<NA / MT, 256, EDGE_SMEM>>>(
            p_q, Wc0 + 128, 384, nullptr, nullptr, nullptr, p_qw);
        // cW = nodes @ Wc0[:,256:384]^T
        hgemm_kernel<false, false, false><<<NN / MT, 256, EDGE_SMEM>>>(
            nodes, Wc0 + 256, 384, nullptr, nullptr, nullptr, p_cw);
        // a = actors @ Wagt^T
        hgemm_kernel<false, false, false><<<NA / MT, 256, EDGE_SMEM>>>(
            cur, agt_W + i * DD, 128, nullptr, nullptr, nullptr, p_a);
        // fused edge chain (HMMA) + scatter into a
        edge_mma_kernel<<<NE / MT, 256, EDGE_SMEM>>>(
            actor_ctrs, node_ctrs, hi, wi,
            dist0_W + i * D * 2, dist0_b + i * D,
            dist1_W + i * DD, dist1_g + i * D, dist1_b + i * D,
            Wc0, ctx0_g + i * D, ctx0_b + i * D,
            ctx1_W + i * DD);
        // x = relu(GN(a))
        gnrows_kernel<<<NA / 8, 256>>>(p_a, norm_g + i * D, norm_b + i * D, p_x);
        // out = relu(GN(x @ Wlin^T) + res)
        hgemm_kernel<true, true, true><<<NA / MT, 256, EDGE_SMEM>>>(
            p_x, lin_W + i * DD, 128, lin_g + i * D, lin_b + i * D, cur, nxt);
    }
}

// round 10
// speedup vs baseline: 3.3765x; 1.0220x over previous
#include <cuda_runtime.h>
#include <cstdint>

#define NA 8192
#define NN 65536
#define NE 262144
#define D  128
#define NB 2
#define MT  128          // rows per HMMA CTA
#define SA  68           // smem pair stride (64 pairs + 4 pad -> conflict-free)
#define EPS 1e-5f

// ---------------- scratch (device globals; no allocation allowed) ------------
__device__ float g_q [NA * D];   // relu(GN(actors @ Wq^T))
__device__ float g_qw[NA * D];   // g_q @ Wc0[:,128:256]^T
__device__ float g_cw[NN * D];   // nodes @ Wc0[:,256:384]^T
__device__ float g_a [NA * D];   // actors @ Wagt^T (+ scattered messages)
__device__ float g_x [NA * D];
__device__ float g_act[NA * D];

// ----------------------------- bf16 helpers ----------------------------------
__device__ __forceinline__ uint32_t pk(float e, float o) {
    uint32_t r;
    asm("cvt.rn.bf16x2.f32 %0, %1, %2;" : "=r"(r) : "f"(o), "f"(e));
    return r;  // lo16 = e (even k), hi16 = o (odd k)
}
__device__ __forceinline__ float lo16f(uint32_t p) { return __uint_as_float(p << 16); }
__device__ __forceinline__ float hi16f(uint32_t p) { return __uint_as_float(p & 0xffff0000u); }

__device__ __forceinline__ uint32_t su32(const void* p) {
    uint32_t a;
    asm("{ .reg .u64 t; cvta.to.shared.u64 t, %1; cvt.u32.u64 %0, t; }"
        : "=r"(a) : "l"(p));
    return a;
}

__device__ __forceinline__ void mma16816(float& c0, float& c1, float& c2, float& c3,
                                         uint32_t a0, uint32_t a1, uint32_t a2, uint32_t a3,
                                         uint32_t b0, uint32_t b1) {
    asm volatile(
        "mma.sync.aligned.m16n8k16.row.col.f32.bf16.bf16.f32 "
        "{%0,%1,%2,%3}, {%4,%5,%6,%7}, {%8,%9}, {%0,%1,%2,%3};"
        : "+f"(c0), "+f"(c1), "+f"(c2), "+f"(c3)
        : "r"(a0), "r"(a1), "r"(a2), "r"(a3), "r"(b0), "r"(b1));
}

__device__ __forceinline__ void ldm4(uint32_t* r, uint32_t a) {
    asm volatile("ldmatrix.sync.aligned.m8n8.x4.shared.b16 {%0,%1,%2,%3}, [%4];"
                 : "=r"(r[0]), "=r"(r[1]), "=r"(r[2]), "=r"(r[3]) : "r"(a));
}

// stage one [128 x 128] fp32 matrix chunk -> bf16 hi/lo pair buffers
__device__ __forceinline__ void stageB(const float* __restrict__ W, int rowlen,
                                       uint32_t* __restrict__ Bh,
                                       uint32_t* __restrict__ Bl) {
    const int t = threadIdx.x;
    const int n = t >> 1, kh = (t & 1) << 6;
    const float4* src = reinterpret_cast<const float4*>(W + (size_t)n * rowlen + kh);
    const int pb = n * SA + ((t & 1) << 5);
#pragma unroll
    for (int i = 0; i < 16; i++) {
        float4 v = src[i];
        uint32_t h0 = pk(v.x, v.y), h1 = pk(v.z, v.w);
        Bh[pb + 2 * i]     = h0;
        Bh[pb + 2 * i + 1] = h1;
        Bl[pb + 2 * i]     = pk(v.x - lo16f(h0), v.y - hi16f(h0));
        Bl[pb + 2 * i + 1] = pk(v.z - lo16f(h1), v.w - hi16f(h1));
    }
}

// 3-term emulated fp32 GEMM via ldmatrix: C[128x128] += A[128x128] @ B^T
// warp (wM 0..3, wN 0..1): rows wM*32..+31 (2 m-tiles), cols wN*64..+63.
__device__ __forceinline__ void do_gemm(
    const uint32_t* Ah, const uint32_t* Al,
    const uint32_t* Bh, const uint32_t* Bl,
    int wM, int wN, int lane, float (&c)[2][8][4]) {
    // A ldmatrix addressing: lanes 0-15 -> rows 0-15 @k0, lanes 16-31 -> rows @k+8
    const int lr = lane & 15;
    const uint32_t khA = (uint32_t)((lane >> 4) << 4);  // +16 bytes for k-high half
    uint32_t aHi0 = su32(Ah) + (uint32_t)((wM * 32 + lr) * SA * 4) + khA;
    uint32_t aHi1 = aHi0 + 16 * SA * 4;
    uint32_t aLo0 = su32(Al) + (uint32_t)((wM * 32 + lr) * SA * 4) + khA;
    uint32_t aLo1 = aLo0 + 16 * SA * 4;
    // B ldmatrix addressing: covers 2 n-octets (nf pair) per x4:
    // lanes 0-7: n0+lane @k0 ; 8-15: n0+lane-8 @k+8 ; 16-23: n0+8+.. @k0 ; 24-31 @k+8
    const int bn = (lane & 7) + ((lane >> 4) << 3);
    const uint32_t khB = (uint32_t)(((lane >> 3) & 1) << 4);
    uint32_t bHi = su32(Bh) + (uint32_t)((wN * 64 + bn) * SA * 4) + khB;
    uint32_t bLo = su32(Bl) + (uint32_t)((wN * 64 + bn) * SA * 4) + khB;

    for (int s = 0; s < 8; s++) {
        const uint32_t off = (uint32_t)(s * 32);  // 8 k-pairs = 32 bytes
        uint32_t ah0[4], ah1[4], al0[4], al1[4];
        ldm4(ah0, aHi0 + off);
        ldm4(ah1, aHi1 + off);
        ldm4(al0, aLo0 + off);
        ldm4(al1, aLo1 + off);
#pragma unroll
        for (int j = 0; j < 4; j++) {
            uint32_t bh[4], bl[4];
            ldm4(bh, bHi + off + (uint32_t)(j * 16 * SA * 4));
            ldm4(bl, bLo + off + (uint32_t)(j * 16 * SA * 4));
            const int n0 = 2 * j, n1 = 2 * j + 1;
            mma16816(c[0][n0][0], c[0][n0][1], c[0][n0][2], c[0][n0][3],
                     al0[0], al0[1], al0[2], al0[3], bh[0], bh[1]);
            mma16816(c[0][n0][0], c[0][n0][1], c[0][n0][2], c[0][n0][3],
                     ah0[0], ah0[1], ah0[2], ah0[3], bl[0], bl[1]);
            mma16816(c[0][n0][0], c[0][n0][1], c[0][n0][2], c[0][n0][3],
                     ah0[0], ah0[1], ah0[2], ah0[3], bh[0], bh[1]);
            mma16816(c[1][n0][0], c[1][n0][1], c[1][n0][2], c[1][n0][3],
                     al1[0], al1[1], al1[2], al1[3], bh[0], bh[1]);
            mma16816(c[1][n0][0], c[1][n0][1], c[1][n0][2], c[1][n0][3],
                     ah1[0], ah1[1], ah1[2], ah1[3], bl[0], bl[1]);
            mma16816(c[1][n0][0], c[1][n0][1], c[1][n0][2], c[1][n0][3],
                     ah1[0], ah1[1], ah1[2], ah1[3], bh[0], bh[1]);
            mma16816(c[0][n1][0], c[0][n1][1], c[0][n1][2], c[0][n1][3],
                     al0[0], al0[1], al0[2], al0[3], bh[2], bh[3]);
            mma16816(c[0][n1][0], c[0][n1][1], c[0][n1][2], c[0][n1][3],
                     ah0[0], ah0[1], ah0[2], ah0[3], bl[2], bl[3]);
            mma16816(c[0][n1][0], c[0][n1][1], c[0][n1][2], c[0][n1][3],
                     ah0[0], ah0[1], ah0[2], ah0[3], bh[2], bh[3]);
            mma16816(c[1][n1][0], c[1][n1][1], c[1][n1][2], c[1][n1][3],
                     al1[0], al1[1], al1[2], al1[3], bh[2], bh[3]);
            mma16816(c[1][n1][0], c[1][n1][1], c[1][n1][2], c[1][n1][3],
                     ah1[0], ah1[1], ah1[2], ah1[3], bl[2], bl[3]);
            mma16816(c[1][n1][0], c[1][n1][1], c[1][n1][2], c[1][n1][3],
                     ah1[0], ah1[1], ah1[2], ah1[3], bh[2], bh[3]);
        }
    }
}

// GN(+relu) epilogue over C; writes normalized bf16 hi/lo back to A pairs 0..63
__device__ __forceinline__ void epi_gn(
    float (&c)[2][8][4], const float* __restrict__ sG, const float* __restrict__ sB,
    uint32_t* __restrict__ Ah, uint32_t* __restrict__ Al,
    float (*sSum)[MT], float (*sSq)[MT], int wM, int wN, int g, int tq) {
    float s_[2][2] = {{0, 0}, {0, 0}}, q_[2][2] = {{0, 0}, {0, 0}};
#pragma unroll
    for (int m = 0; m < 2; m++)
#pragma unroll
        for (int nf = 0; nf < 8; nf++) {
            float v0 = c[m][nf][0], v1 = c[m][nf][1];
            float v2 = c[m][nf][2], v3 = c[m][nf][3];
            s_[m][0] += v0 + v1;
            q_[m][0] = fmaf(v0, v0, fmaf(v1, v1, q_[m][0]));
            s_[m][1] += v2 + v3;
            q_[m][1] = fmaf(v2, v2, fmaf(v3, v3, q_[m][1]));
        }
#pragma unroll
    for (int m = 0; m < 2; m++)
#pragma unroll
        for (int h = 0; h < 2; h++) {
            s_[m][h] += __shfl_xor_sync(0xffffffffu, s_[m][h], 1);
            s_[m][h] += __shfl_xor_sync(0xffffffffu, s_[m][h], 2);
            q_[m][h] += __shfl_xor_sync(0xffffffffu, q_[m][h], 1);
            q_[m][h] += __shfl_xor_sync(0xffffffffu, q_[m][h], 2);
        }
    if (tq == 0) {
#pragma unroll
        for (int m = 0; m < 2; m++)
#pragma unroll
            for (int h = 0; h < 2; h++) {
                int row = wM * 32 + m * 16 + g + 8 * h;
                sSum[wN][row] = s_[m][h];
                sSq[wN][row]  = q_[m][h];
            }
    }
    __syncthreads();
    float mu[2][2], rs[2][2];
#pragma unroll
    for (int m = 0; m < 2; m++)
#pragma unroll
        for (int h = 0; h < 2; h++) {
            int row = wM * 32 + m * 16 + g + 8 * h;
            float S = sSum[0][row] + sSum[1][row];
            float Q = sSq[0][row] + sSq[1][row];
            mu[m][h] = S * (1.0f / 128.0f);
            rs[m][h] = rsqrtf(Q * (1.0f / 128.0f) - mu[m][h] * mu[m][h] + EPS);
        }
#pragma unroll
    for (int m = 0; m < 2; m++) {
        const int rb = wM * 32 + m * 16 + g;
#pragma unroll
        for (int nf = 0; nf < 8; nf++) {
            const int ch = wN * 64 + nf * 8 + 2 * tq;
            const float g0 = sG[ch], g1 = sG[ch + 1];
            const float b0 = sB[ch], b1 = sB[ch + 1];
            const int p = wN * 32 + nf * 4 + tq;
            float e = fmaxf((c[m][nf][0] - mu[m][0]) * rs[m][0] * g0 + b0, 0.0f);
            float o = fmaxf((c[m][nf][1] - mu[m][0]) * rs[m][0] * g1 + b1, 0.0f);
            uint32_t hp = pk(e, o);
            Ah[rb * SA + p] = hp;
            Al[rb * SA + p] = pk(e - lo16f(hp), o - hi16f(hp));
            e = fmaxf((c[m][nf][2] - mu[m][1]) * rs[m][1] * g0 + b0, 0.0f);
            o = fmaxf((c[m][nf][3] - mu[m][1]) * rs[m][1] * g1 + b1, 0.0f);
            hp = pk(e, o);
            Ah[(rb + 8) * SA + p] = hp;
            Al[(rb + 8) * SA + p] = pk(e - lo16f(hp), o - hi16f(hp));
        }
    }
}

// ============================ edge kernel (HMMA) =============================
__global__ void __launch_bounds__(256, 1) edge_mma_kernel(
    const float* __restrict__ actor_ctrs, const float* __restrict__ node_ctrs,
    const int* __restrict__ hi, const int* __restrict__ wi,
    const float* __restrict__ W0, const float* __restrict__ b0,
    const float* __restrict__ W1, const float* __restrict__ g1, const float* __restrict__ b1v,
    const float* __restrict__ Wc0d, const float* __restrict__ gc0, const float* __restrict__ bc0,
    const float* __restrict__ Wc1) {
    extern __shared__ uint32_t smu[];
    uint32_t* Ah = smu;
    uint32_t* Al = smu + 128 * SA;
    uint32_t* Bh = smu + 2 * 128 * SA;
    uint32_t* Bl = smu + 3 * 128 * SA;
    __shared__ float sW0[2 * D], sB0[D], sG1[D], sB1[D], sGc[D], sBc[D];
    __shared__ int sHi[MT], sWi[MT];
    __shared__ float sSum[2][MT], sSq[2][MT];

    const int tid = threadIdx.x;
    const int lane = tid & 31, wid = tid >> 5;
    const int wN = wid & 1, wM = wid >> 1;
    const int g = lane >> 2, tq = lane & 3;
    const int e0 = blockIdx.x * MT;

    sW0[tid] = W0[tid];
    if (tid < D) {
        sB0[tid] = b0[tid]; sG1[tid] = g1[tid]; sB1[tid] = b1v[tid];
        sGc[tid] = gc0[tid]; sBc[tid] = bc0[tid];
        sHi[tid] = hi[e0 + tid]; sWi[tid] = wi[e0 + tid];
    }
    __syncthreads();

    // ---- phase 0: h -> A pairs 0..63 ; stage B = W1 ----
    {
        const int row = tid >> 1, hf = tid & 1;
        const int h_ = sHi[row], w_ = sWi[row];
        float2 ac = reinterpret_cast<const float2*>(actor_ctrs)[h_];
        float2 nc = reinterpret_cast<const float2*>(node_ctrs)[w_];
        float dx = ac.x - nc.x, dy = ac.y - nc.y;
#pragma unroll
        for (int i = 0; i < 32; i++) {
            int ch = hf * 64 + 2 * i;
            float e = fmaxf(fmaf(dx, sW0[2 * ch],     fmaf(dy, sW0[2 * ch + 1], sB0[ch])),     0.0f);
            float o = fmaxf(fmaf(dx, sW0[2 * ch + 2], fmaf(dy, sW0[2 * ch + 3], sB0[ch + 1])), 0.0f);
            uint32_t hp = pk(e, o);
            Ah[row * SA + hf * 32 + i] = hp;
            Al[row * SA + hf * 32 + i] = pk(e - lo16f(hp), o - hi16f(hp));
        }
    }
    stageB(W1, 128, Bh, Bl);
    __syncthreads();

    float c[2][8][4];

    // ---- GEMM1: d_pre = h @ W1^T ----
#pragma unroll
    for (int m = 0; m < 2; m++)
#pragma unroll
        for (int nf = 0; nf < 8; nf++)
#pragma unroll
            for (int j = 0; j < 4; j++) c[m][nf][j] = 0.0f;
    do_gemm(Ah, Al, Bh, Bl, wM, wN, lane, c);
    epi_gn(c, sG1, sB1, Ah, Al, sSum, sSq, wM, wN, g, tq);
    stageB(Wc0d, 384, Bh, Bl);
    __syncthreads();

    // ---- GEMM2: u_pre = d @ Wc0d^T + qW[hi] + cW[wi] ----
#pragma unroll
    for (int m = 0; m < 2; m++)
#pragma unroll
        for (int h = 0; h < 2; h++) {
            int row = wM * 32 + m * 16 + g + 8 * h;
            const float2* qp = reinterpret_cast<const float2*>(
                g_qw + (size_t)sHi[row] * D + wN * 64);
            const float2* cp = reinterpret_cast<const float2*>(
                g_cw + (size_t)sWi[row] * D + wN * 64);
#pragma unroll
            for (int nf = 0; nf < 8; nf++) {
                float2 a_ = qp[nf * 4 + tq];
                float2 b_ = cp[nf * 4 + tq];
                c[m][nf][2 * h]     = a_.x + b_.x;
                c[m][nf][2 * h + 1] = a_.y + b_.y;
            }
        }
    do_gemm(Ah, Al, Bh, Bl, wM, wN, lane, c);
    epi_gn(c, sGc, sBc, Ah, Al, sSum, sSq, wM, wN, g, tq);
    stageB(Wc1, 128, Bh, Bl);
    __syncthreads();

    // ---- GEMM3: m = u @ Wc1^T ; scatter ----
#pragma unroll
    for (int m = 0; m < 2; m++)
#pragma unroll
        for (int nf = 0; nf < 8; nf++)
#pragma unroll
            for (int j = 0; j < 4; j++) c[m][nf][j] = 0.0f;
    do_gemm(Ah, Al, Bh, Bl, wM, wN, lane, c);
#pragma unroll
    for (int m = 0; m < 2; m++)
#pragma unroll
        for (int h = 0; h < 2; h++) {
            int row = wM * 32 + m * 16 + g + 8 * h;
            float* base = g_a + (size_t)sHi[row] * D + wN * 64;
#pragma unroll
            for (int nf = 0; nf < 8; nf++) {
                int ch = nf * 8 + 2 * tq;
                atomicAdd(base + ch,     c[m][nf][2 * h]);
                atomicAdd(base + ch + 1, c[m][nf][2 * h + 1]);
            }
        }
}

// ================= HMMA row-GEMM: out[128,128] = f(in @ W^T) =================
template <bool GN, bool RELU, bool RES>
__global__ void __launch_bounds__(256, 1) hgemm_kernel(
    const float* __restrict__ in, const float* __restrict__ W, int wstride,
    const float* __restrict__ gw, const float* __restrict__ bw,
    const float* __restrict__ res, float* __restrict__ out) {
    extern __shared__ uint32_t smu[];
    uint32_t* Ah = smu;
    uint32_t* Al = smu + 128 * SA;
    uint32_t* Bh = smu + 2 * 128 * SA;
    uint32_t* Bl = smu + 3 * 128 * SA;
    __shared__ float sG[D], sB[D];
    __shared__ float sSum[2][MT], sSq[2][MT];

    const int tid = threadIdx.x;
    const int lane = tid & 31, wid = tid >> 5;
    const int wN = wid & 1, wM = wid >> 1;
    const int g = lane >> 2, tq = lane & 3;
    const size_t r0 = (size_t)blockIdx.x * MT;

    if (GN && tid < D) { sG[tid] = gw[tid]; sB[tid] = bw[tid]; }
    stageB(in + r0 * D, 128, Ah, Al);
    stageB(W, wstride, Bh, Bl);
    __syncthreads();

    float c[2][8][4];
#pragma unroll
    for (int m = 0; m < 2; m++)
#pragma unroll
        for (int nf = 0; nf < 8; nf++)
#pragma unroll
            for (int j = 0; j < 4; j++) c[m][nf][j] = 0.0f;
    do_gemm(Ah, Al, Bh, Bl, wM, wN, lane, c);

    if (GN) {
        float s_[2][2] = {{0, 0}, {0, 0}}, q_[2][2] = {{0, 0}, {0, 0}};
#pragma unroll
        for (int m = 0; m < 2; m++)
#pragma unroll
            for (int nf = 0; nf < 8; nf++) {
                float v0 = c[m][nf][0], v1 = c[m][nf][1];
                float v2 = c[m][nf][2], v3 = c[m][nf][3];
                s_[m][0] += v0 + v1;
                q_[m][0] = fmaf(v0, v0, fmaf(v1, v1, q_[m][0]));
                s_[m][1] += v2 + v3;
                q_[m][1] = fmaf(v2, v2, fmaf(v3, v3, q_[m][1]));
            }
#pragma unroll
        for (int m = 0; m < 2; m++)
#pragma unroll
            for (int h = 0; h < 2; h++) {
                s_[m][h] += __shfl_xor_sync(0xffffffffu, s_[m][h], 1);
                s_[m][h] += __shfl_xor_sync(0xffffffffu, s_[m][h], 2);
                q_[m][h] += __shfl_xor_sync(0xffffffffu, q_[m][h], 1);
                q_[m][h] += __shfl_xor_sync(0xffffffffu, q_[m][h], 2);
            }
        if (tq == 0) {
#pragma unroll
            for (int m = 0; m < 2; m++)
#pragma unroll
                for (int h = 0; h < 2; h++) {
                    int row = wM * 32 + m * 16 + g + 8 * h;
                    sSum[wN][row] = s_[m][h];
                    sSq[wN][row]  = q_[m][h];
                }
        }
        __syncthreads();
#pragma unroll
        for (int m = 0; m < 2; m++)
#pragma unroll
            for (int h = 0; h < 2; h++) {
                int row = wM * 32 + m * 16 + g + 8 * h;
                float S = sSum[0][row] + sSum[1][row];
                float Q = sSq[0][row] + sSq[1][row];
                float mu = S * (1.0f / 128.0f);
                float rs = rsqrtf(Q * (1.0f / 128.0f) - mu * mu + EPS);
                float* op = out + (r0 + row) * D;
                const float* rp = RES ? res + (r0 + row) * D : nullptr;
#pragma unroll
                for (int nf = 0; nf < 8; nf++) {
                    int ch = wN * 64 + nf * 8 + 2 * tq;
                    float y0 = (c[m][nf][2 * h]     - mu) * rs * sG[ch]     + sB[ch];
                    float y1 = (c[m][nf][2 * h + 1] - mu) * rs * sG[ch + 1] + sB[ch + 1];
                    if (RES) { y0 += rp[ch]; y1 += rp[ch + 1]; }
                    if (RELU) { y0 = fmaxf(y0, 0.0f); y1 = fmaxf(y1, 0.0f); }
                    *reinterpret_cast<float2*>(op + ch) = make_float2(y0, y1);
                }
            }
    } else {
#pragma unroll
        for (int m = 0; m < 2; m++)
#pragma unroll
            for (int h = 0; h < 2; h++) {
                int row = wM * 32 + m * 16 + g + 8 * h;
                float* op = out + (r0 + row) * D;
#pragma unroll
                for (int nf = 0; nf < 8; nf++) {
                    int ch = wN * 64 + nf * 8 + 2 * tq;
                    float y0 = c[m][nf][2 * h], y1 = c[m][nf][2 * h + 1];
                    if (RELU) { y0 = fmaxf(y0, 0.0f); y1 = fmaxf(y1, 0.0f); }
                    *reinterpret_cast<float2*>(op + ch) = make_float2(y0, y1);
                }
            }
    }
}

// x = relu(GN(a)) ; one warp per row
__global__ void __launch_bounds__(256) gnrows_kernel(
    const float* __restrict__ in, const float* __restrict__ g,
    const float* __restrict__ bb, float* __restrict__ out) {
    const int lane = threadIdx.x & 31;
    const int row = blockIdx.x * 8 + (threadIdx.x >> 5);
    const float* x = in + (size_t)row * D;
    float v0 = x[lane], v1 = x[lane + 32], v2 = x[lane + 64], v3 = x[lane + 96];
    float s = v0 + v1 + v2 + v3;
    float q = fmaf(v0, v0, fmaf(v1, v1, fmaf(v2, v2, v3 * v3)));
#pragma unroll
    for (int o = 16; o > 0; o >>= 1) {
        s += __shfl_xor_sync(0xffffffffu, s, o);
        q += __shfl_xor_sync(0xffffffffu, q, o);
    }
    float mu = s * (1.0f / 128.0f);
    float rs = rsqrtf(q * (1.0f / 128.0f) - mu * mu + EPS);
    float* o_ = out + (size_t)row * D;
    o_[lane]      = fmaxf((v0 - mu) * rs * g[lane] + bb[lane], 0.0f);
    o_[lane + 32] = fmaxf((v1 - mu) * rs * g[lane + 32] + bb[lane + 32], 0.0f);
    o_[lane + 64] = fmaxf((v2 - mu) * rs * g[lane + 64] + bb[lane + 64], 0.0f);
    o_[lane + 96] = fmaxf((v3 - mu) * rs * g[lane + 96] + bb[lane + 96], 0.0f);
}

#define EDGE_SMEM (4 * 128 * SA * 4)

extern "C" void kernel_launch(void* const* d_in, const int* in_sizes, int n_in,
                              void* d_out, int out_size) {
    (void)in_sizes; (void)n_in; (void)out_size;
    const float* actors     = (const float*)d_in[0];
    const float* nodes      = (const float*)d_in[1];
    const float* actor_ctrs = (const float*)d_in[2];
    const float* node_ctrs  = (const float*)d_in[3];
    const int*   hi         = (const int*)d_in[4];
    const int*   wi         = (const int*)d_in[5];
    const float* dist0_W = (const float*)d_in[6];
    const float* dist0_b = (const float*)d_in[7];
    const float* dist1_W = (const float*)d_in[8];
    const float* dist1_g = (const float*)d_in[9];
    const float* dist1_b = (const float*)d_in[10];
    const float* query_W = (const float*)d_in[11];
    const float* query_g = (const float*)d_in[12];
    const float* query_b = (const float*)d_in[13];
    const float* ctx0_W  = (const float*)d_in[14];
    const float* ctx0_g  = (const float*)d_in[15];
    const float* ctx0_b  = (const float*)d_in[16];
    const float* ctx1_W  = (const float*)d_in[17];
    const float* agt_W   = (const float*)d_in[18];
    const float* norm_g  = (const float*)d_in[19];
    const float* norm_b  = (const float*)d_in[20];
    const float* lin_W   = (const float*)d_in[21];
    const float* lin_g   = (const float*)d_in[22];
    const float* lin_b   = (const float*)d_in[23];
    float* outp = (float*)d_out;

    void *pq_, *pqw_, *pcw_, *pa_, *px_, *pact_;
    cudaGetSymbolAddress(&pq_, g_q);
    cudaGetSymbolAddress(&pqw_, g_qw);
    cudaGetSymbolAddress(&pcw_, g_cw);
    cudaGetSymbolAddress(&pa_, g_a);
    cudaGetSymbolAddress(&px_, g_x);
    cudaGetSymbolAddress(&pact_, g_act);
    float* p_q   = (float*)pq_;
    float* p_qw  = (float*)pqw_;
    float* p_cw  = (float*)pcw_;
    float* p_a   = (float*)pa_;
    float* p_x   = (float*)px_;
    float* p_act = (float*)pact_;

    cudaFuncSetAttribute(edge_mma_kernel,
                         cudaFuncAttributeMaxDynamicSharedMemorySize, EDGE_SMEM);
    cudaFuncSetAttribute(hgemm_kernel<true, true, false>,
                         cudaFuncAttributeMaxDynamicSharedMemorySize, EDGE_SMEM);
    cudaFuncSetAttribute(hgemm_kernel<false, false, false>,
                         cudaFuncAttributeMaxDynamicSharedMemorySize, EDGE_SMEM);
    cudaFuncSetAttribute(hgemm_kernel<true, true, true>,
                         cudaFuncAttributeMaxDynamicSharedMemorySize, EDGE_SMEM);

    const int DD = D * D;
    for (int i = 0; i < NB; i++) {
        const float* cur = (i == 0) ? actors : p_act;
        float* nxt = (i == NB - 1) ? outp : p_act;
        const float* Wc0 = ctx0_W + (size_t)i * D * 3 * D;

        // q = relu(GN(actors @ Wq^T))
        hgemm_kernel<true, true, false><<<NA / MT, 256, EDGE_SMEM>>>(
            cur, query_W + i * DD, 128, query_g + i * D, query_b + i * D, nullptr, p_q);
        // qW = q @ Wc0[:,128:256]^T
        hgemm_kernel<false, false, false><<<NA / MT, 256, EDGE_SMEM>>>(
            p_q, Wc0 + 128, 384, nullptr, nullptr, nullptr, p_qw);
        // cW = nodes @ Wc0[:,256:384]^T
        hgemm_kernel<false, false, false><<<NN / MT, 256, EDGE_SMEM>>>(
            nodes, Wc0 + 256, 384, nullptr, nullptr, nullptr, p_cw);
        // a = actors @ Wagt^T
        hgemm_kernel<false, false, false><<<NA / MT, 256, EDGE_SMEM>>>(
            cur, agt_W + i * DD, 128, nullptr, nullptr, nullptr, p_a);
        // fused edge chain (HMMA) + scatter into a
        edge_mma_kernel<<<NE / MT, 256, EDGE_SMEM>>>(
            actor_ctrs, node_ctrs, hi, wi,
            dist0_W + i * D * 2, dist0_b + i * D,
            dist1_W + i * DD, dist1_g + i * D, dist1_b + i * D,
            Wc0, ctx0_g + i * D, ctx0_b + i * D,
            ctx1_W + i * DD);
        // x = relu(GN(a))
        gnrows_kernel<<<NA / 8, 256>>>(p_a, norm_g + i * D, norm_b + i * D, p_x);
        // out = relu(GN(x @ Wlin^T) + res)
        hgemm_kernel<true, true, true><<<NA / MT, 256, EDGE_SMEM>>>(
            p_x, lin_W + i * DD, 128, lin_g + i * D, lin_b + i * D, cur, nxt);
    }
}